// round 2
// baseline (speedup 1.0000x reference)
#include <cuda_runtime.h>
#include <math.h>

#define D_   128
#define H_   4
#define HD_  512
#define ED_  16
#define MAXN 50000
#define MAXE 150000

// ---------------- scratch (device globals; no allocations allowed) ----------------
__device__ float g_q[(size_t)MAXN * HD_];
__device__ float g_k[(size_t)MAXN * HD_];
__device__ float g_v[(size_t)MAXN * HD_];
__device__ float g_g[(size_t)MAXN * HD_];
__device__ float g_xsr[(size_t)MAXN * D_];
__device__ float g_skip[(size_t)MAXN * D_];
__device__ float g_mean[(size_t)MAXN * D_];
__device__ float g_sWl[(size_t)MAXN * D_];
__device__ float g_fpre[(size_t)MAXN * D_];
__device__ float g_xcat[(size_t)MAXN * 3 * D_];
__device__ float g_as[MAXN * H_];
__device__ float g_ad[MAXN * H_];
__device__ int   g_deg[MAXN];
__device__ int   g_cur[MAXN];
__device__ int   g_rowptr[MAXN + 1];
__device__ int   g_eidx[MAXE];

__device__ __forceinline__ float wredsum(float v) {
    v += __shfl_xor_sync(0xffffffffu, v, 16);
    v += __shfl_xor_sync(0xffffffffu, v, 8);
    v += __shfl_xor_sync(0xffffffffu, v, 4);
    v += __shfl_xor_sync(0xffffffffu, v, 2);
    v += __shfl_xor_sync(0xffffffffu, v, 1);
    return v;
}

__device__ __forceinline__ float lrelu02(float x) { return x > 0.f ? x : 0.2f * x; }
__device__ __forceinline__ float sigm(float x) { return 1.f / (1.f + __expf(-x)); }

// ---------------- CSR build ----------------
__global__ void k_zero(int N) {
    int i = blockIdx.x * blockDim.x + threadIdx.x;
    if (i < N) { g_deg[i] = 0; g_cur[i] = 0; }
}

__global__ void k_count(const int* __restrict__ dst, int E) {
    int e = blockIdx.x * blockDim.x + threadIdx.x;
    if (e < E) atomicAdd(&g_deg[dst[e]], 1);
}

__global__ void k_scan(int N) {
    __shared__ int wsum[32];
    __shared__ int carry;
    int tid = threadIdx.x, lane = tid & 31, wid = tid >> 5;
    if (tid == 0) carry = 0;
    __syncthreads();
    for (int base = 0; base < N; base += 1024) {
        int i = base + tid;
        int v = (i < N) ? g_deg[i] : 0;
        int x = v;
        #pragma unroll
        for (int o = 1; o < 32; o <<= 1) {
            int y = __shfl_up_sync(0xffffffffu, x, o);
            if (lane >= o) x += y;
        }
        if (lane == 31) wsum[wid] = x;
        __syncthreads();
        if (wid == 0) {
            int wv = wsum[lane];
            #pragma unroll
            for (int o = 1; o < 32; o <<= 1) {
                int y = __shfl_up_sync(0xffffffffu, wv, o);
                if (lane >= o) wv += y;
            }
            wsum[lane] = wv;
        }
        __syncthreads();
        int woff = (wid > 0) ? wsum[wid - 1] : 0;
        int excl = x - v + woff;
        int c = carry;
        if (i < N) g_rowptr[i] = c + excl;
        int total = wsum[31];
        __syncthreads();
        if (tid == 0) carry = c + total;
        __syncthreads();
    }
    if (threadIdx.x == 0) g_rowptr[N] = carry;
}

__global__ void k_fill(const int* __restrict__ dst, int E) {
    int e = blockIdx.x * blockDim.x + threadIdx.x;
    if (e < E) {
        int d = dst[e];
        int p = atomicAdd(&g_cur[d], 1);
        g_eidx[g_rowptr[d] + p] = e;
    }
}

// ---------------- SGEMM: C[M,Nc] = A[M,K] @ B[K,Nc] (+bias) ----------------
// BM=BN=64, BK=16, 256 threads, 4x4 micro-tile. K%16==0, Nc%64==0.
__global__ void __launch_bounds__(256)
sgemm(const float* __restrict__ A, const float* __restrict__ B,
      const float* __restrict__ bias, float* __restrict__ C,
      int M, int Nc, int K) {
    __shared__ float Ast[16][64];
    __shared__ float Bs[16][64];
    int tid = threadIdx.x;
    int rowStart = blockIdx.y * 64, colStart = blockIdx.x * 64;
    int tx = tid & 15, ty = tid >> 4;
    int aRow = tid >> 2, aCol = (tid & 3) * 4;
    int bRow = tid >> 4, bCol = (tid & 15) * 4;
    float acc[4][4] = {};
    for (int k0 = 0; k0 < K; k0 += 16) {
        float4 av = make_float4(0.f, 0.f, 0.f, 0.f);
        int gr = rowStart + aRow;
        if (gr < M) av = *(const float4*)(A + (size_t)gr * K + k0 + aCol);
        Ast[aCol + 0][aRow] = av.x;
        Ast[aCol + 1][aRow] = av.y;
        Ast[aCol + 2][aRow] = av.z;
        Ast[aCol + 3][aRow] = av.w;
        float4 bv = *(const float4*)(B + (size_t)(k0 + bRow) * Nc + colStart + bCol);
        *(float4*)&Bs[bRow][bCol] = bv;
        __syncthreads();
        #pragma unroll
        for (int kk = 0; kk < 16; kk++) {
            float4 ra4 = *(float4*)&Ast[kk][ty * 4];
            float4 rb4 = *(float4*)&Bs[kk][tx * 4];
            float ra[4] = {ra4.x, ra4.y, ra4.z, ra4.w};
            float rb[4] = {rb4.x, rb4.y, rb4.z, rb4.w};
            #pragma unroll
            for (int i = 0; i < 4; i++)
                #pragma unroll
                for (int j = 0; j < 4; j++)
                    acc[i][j] = fmaf(ra[i], rb[j], acc[i][j]);
        }
        __syncthreads();
    }
    float4 bb = make_float4(0.f, 0.f, 0.f, 0.f);
    if (bias) bb = *(const float4*)(bias + colStart + tx * 4);
    #pragma unroll
    for (int i = 0; i < 4; i++) {
        int r = rowStart + ty * 4 + i;
        if (r < M) {
            float4 o;
            o.x = acc[i][0] + bb.x;
            o.y = acc[i][1] + bb.y;
            o.z = acc[i][2] + bb.z;
            o.w = acc[i][3] + bb.w;
            *(float4*)(C + (size_t)r * Nc + colStart + tx * 4) = o;
        }
    }
}

// ---------------- GAT attention coefficients ----------------
__global__ void k_asad(const float* __restrict__ att_src, const float* __restrict__ att_dst, int N) {
    __shared__ float aS[HD_], aD[HD_];
    for (int i = threadIdx.x; i < HD_; i += blockDim.x) { aS[i] = att_src[i]; aD[i] = att_dst[i]; }
    __syncthreads();
    int warp = (blockIdx.x * blockDim.x + threadIdx.x) >> 5;
    int lane = threadIdx.x & 31;
    if (warp >= N) return;
    int n = warp;
    float ps[4] = {0, 0, 0, 0}, pd[4] = {0, 0, 0, 0};
    #pragma unroll
    for (int t = 0; t < 16; t++) {
        float gv = g_g[(size_t)n * HD_ + lane + 32 * t];
        ps[t >> 2] = fmaf(gv, aS[lane + 32 * t], ps[t >> 2]);
        pd[t >> 2] = fmaf(gv, aD[lane + 32 * t], pd[t >> 2]);
    }
    float s0 = wredsum(ps[0]), s1 = wredsum(ps[1]), s2 = wredsum(ps[2]), s3 = wredsum(ps[3]);
    float d0 = wredsum(pd[0]), d1 = wredsum(pd[1]), d2 = wredsum(pd[2]), d3 = wredsum(pd[3]);
    if (lane == 0) {
        g_as[n * 4 + 0] = s0; g_as[n * 4 + 1] = s1; g_as[n * 4 + 2] = s2; g_as[n * 4 + 3] = s3;
        g_ad[n * 4 + 0] = d0; g_ad[n * 4 + 1] = d1; g_ad[n * 4 + 2] = d2; g_ad[n * 4 + 3] = d3;
    }
}

// ---------------- TransformerConv (online softmax) + SAGE mean, warp per dst node ----------------
__global__ void k_trans_sage(const int* __restrict__ src, const float* __restrict__ ea,
                             const float* __restrict__ te_W, const float* __restrict__ x,
                             const float* __restrict__ gate_attn, int N) {
    __shared__ float te_sm[ED_ * HD_];  // 32 KB
    for (int i = threadIdx.x; i < ED_ * HD_; i += blockDim.x) te_sm[i] = te_W[i];
    __syncthreads();
    int warp = (blockIdx.x * blockDim.x + threadIdx.x) >> 5;
    int lane = threadIdx.x & 31;
    if (warp >= N) return;
    int n = warp;
    int r0 = g_rowptr[n], r1 = g_rowptr[n + 1];
    int deg = r1 - r0;

    float qreg[16], acc[16];
    #pragma unroll
    for (int t = 0; t < 16; t++) {
        qreg[t] = g_q[(size_t)n * HD_ + lane + 32 * t];
        acc[t] = 0.f;
    }
    float m0 = -INFINITY, m1 = -INFINITY, m2 = -INFINITY, m3 = -INFINITY;
    float s0 = 0.f, s1 = 0.f, s2 = 0.f, s3 = 0.f;
    float4 accx = make_float4(0.f, 0.f, 0.f, 0.f);
    const float scale = 0.08838834764831845f;  // 1/sqrt(128)

    for (int ei = r0; ei < r1; ei++) {
        int eid = g_eidx[ei];
        int s = src[eid];
        // SAGE neighbor sum
        float4 xv = *(const float4*)(x + (size_t)s * D_ + (lane << 2));
        accx.x += xv.x; accx.y += xv.y; accx.z += xv.z; accx.w += xv.w;
        // edge embedding e = ea @ te_W (on the fly)
        float eav = (lane < ED_) ? ea[(size_t)eid * ED_ + lane] : 0.f;
        float e[16];
        #pragma unroll
        for (int t = 0; t < 16; t++) e[t] = 0.f;
        #pragma unroll
        for (int j = 0; j < ED_; j++) {
            float a = __shfl_sync(0xffffffffu, eav, j);
            #pragma unroll
            for (int t = 0; t < 16; t++)
                e[t] = fmaf(a, te_sm[j * HD_ + lane + 32 * t], e[t]);
        }
        // logits per head
        float p0 = 0.f, p1 = 0.f, p2 = 0.f, p3 = 0.f;
        #pragma unroll
        for (int t = 0; t < 16; t++) {
            float kv = g_k[(size_t)s * HD_ + lane + 32 * t] + e[t];
            float pr = qreg[t] * kv;
            if (t < 4) p0 += pr; else if (t < 8) p1 += pr; else if (t < 12) p2 += pr; else p3 += pr;
        }
        float l0 = wredsum(p0) * scale;
        float l1 = wredsum(p1) * scale;
        float l2 = wredsum(p2) * scale;
        float l3 = wredsum(p3) * scale;
        // online softmax update
        float n0 = fmaxf(m0, l0), sc0 = __expf(m0 - n0), w0 = __expf(l0 - n0);
        float n1 = fmaxf(m1, l1), sc1 = __expf(m1 - n1), w1 = __expf(l1 - n1);
        float n2 = fmaxf(m2, l2), sc2 = __expf(m2 - n2), w2 = __expf(l2 - n2);
        float n3 = fmaxf(m3, l3), sc3 = __expf(m3 - n3), w3 = __expf(l3 - n3);
        s0 = s0 * sc0 + w0; m0 = n0;
        s1 = s1 * sc1 + w1; m1 = n1;
        s2 = s2 * sc2 + w2; m2 = n2;
        s3 = s3 * sc3 + w3; m3 = n3;
        #pragma unroll
        for (int t = 0; t < 16; t++) {
            float vv = g_v[(size_t)s * HD_ + lane + 32 * t] + e[t];
            float sc = (t < 4) ? sc0 : (t < 8) ? sc1 : (t < 12) ? sc2 : sc3;
            float w  = (t < 4) ? w0  : (t < 8) ? w1  : (t < 12) ? w2  : w3;
            acc[t] = fmaf(acc[t], sc, w * vv);
        }
    }
    // finalize: mean over heads, + skip, relu, * sigmoid(gate_attn)
    float ga = sigm(gate_attn[0]);
    float i0 = 1.f / (s0 + 1e-16f);
    float i1 = 1.f / (s1 + 1e-16f);
    float i2 = 1.f / (s2 + 1e-16f);
    float i3 = 1.f / (s3 + 1e-16f);
    #pragma unroll
    for (int t0 = 0; t0 < 4; t0++) {
        float od = 0.25f * (acc[t0] * i0 + acc[t0 + 4] * i1 + acc[t0 + 8] * i2 + acc[t0 + 12] * i3);
        int d = lane + 32 * t0;
        float val = fmaxf(od + g_skip[(size_t)n * D_ + d], 0.f) * ga;
        g_xcat[(size_t)n * 384 + 128 + d] = val;
    }
    float invd = 1.f / fmaxf((float)deg, 1.f);
    float4 mv = make_float4(accx.x * invd, accx.y * invd, accx.z * invd, accx.w * invd);
    *(float4*)(g_mean + (size_t)n * D_ + (lane << 2)) = mv;
}

// ---------------- GAT (self-loops + online softmax), warp per dst node ----------------
__global__ void k_gat(const int* __restrict__ src, const float* __restrict__ gat_bias,
                      const float* __restrict__ gate_nb, int N) {
    int warp = (blockIdx.x * blockDim.x + threadIdx.x) >> 5;
    int lane = threadIdx.x & 31;
    if (warp >= N) return;
    int n = warp;
    float ad0 = g_ad[n * 4 + 0], ad1 = g_ad[n * 4 + 1], ad2 = g_ad[n * 4 + 2], ad3 = g_ad[n * 4 + 3];
    float as0 = g_as[n * 4 + 0], as1 = g_as[n * 4 + 1], as2 = g_as[n * 4 + 2], as3 = g_as[n * 4 + 3];
    // init with self-loop
    float m0 = lrelu02(as0 + ad0), m1 = lrelu02(as1 + ad1);
    float m2 = lrelu02(as2 + ad2), m3 = lrelu02(as3 + ad3);
    float s0 = 1.f, s1 = 1.f, s2 = 1.f, s3 = 1.f;
    float acc[16];
    #pragma unroll
    for (int t = 0; t < 16; t++) acc[t] = g_g[(size_t)n * HD_ + lane + 32 * t];
    int r0 = g_rowptr[n], r1 = g_rowptr[n + 1];
    for (int ei = r0; ei < r1; ei++) {
        int s = src[g_eidx[ei]];
        float l0 = lrelu02(g_as[s * 4 + 0] + ad0);
        float l1 = lrelu02(g_as[s * 4 + 1] + ad1);
        float l2 = lrelu02(g_as[s * 4 + 2] + ad2);
        float l3 = lrelu02(g_as[s * 4 + 3] + ad3);
        float n0 = fmaxf(m0, l0), sc0 = __expf(m0 - n0), w0 = __expf(l0 - n0);
        float n1 = fmaxf(m1, l1), sc1 = __expf(m1 - n1), w1 = __expf(l1 - n1);
        float n2 = fmaxf(m2, l2), sc2 = __expf(m2 - n2), w2 = __expf(l2 - n2);
        float n3 = fmaxf(m3, l3), sc3 = __expf(m3 - n3), w3 = __expf(l3 - n3);
        s0 = s0 * sc0 + w0; m0 = n0;
        s1 = s1 * sc1 + w1; m1 = n1;
        s2 = s2 * sc2 + w2; m2 = n2;
        s3 = s3 * sc3 + w3; m3 = n3;
        #pragma unroll
        for (int t = 0; t < 16; t++) {
            float sc = (t < 4) ? sc0 : (t < 8) ? sc1 : (t < 12) ? sc2 : sc3;
            float w  = (t < 4) ? w0  : (t < 8) ? w1  : (t < 12) ? w2  : w3;
            acc[t] = fmaf(acc[t], sc, w * g_g[(size_t)s * HD_ + lane + 32 * t]);
        }
    }
    float gn = sigm(gate_nb[0]);
    float i0 = 1.f / (s0 + 1e-16f);
    float i1 = 1.f / (s1 + 1e-16f);
    float i2 = 1.f / (s2 + 1e-16f);
    float i3 = 1.f / (s3 + 1e-16f);
    #pragma unroll
    for (int t0 = 0; t0 < 4; t0++) {
        float od = 0.25f * (acc[t0] * i0 + acc[t0 + 4] * i1 + acc[t0 + 8] * i2 + acc[t0 + 12] * i3);
        int d = lane + 32 * t0;
        float val = fmaxf(od + gat_bias[d], 0.f) * gn;
        g_xcat[(size_t)n * 384 + 256 + d] = val;
    }
}

// ---------------- short branch: relu(mean@Wl + x@Wr + b) * sigmoid(gate_short) ----------------
__global__ void k_short(const float* __restrict__ gate_short, int N) {
    int i = blockIdx.x * blockDim.x + threadIdx.x;
    if (i >= N * D_) return;
    float gs = sigm(gate_short[0]);
    int n = i >> 7, d = i & 127;
    g_xcat[(size_t)n * 384 + d] = fmaxf(g_sWl[i] + g_xsr[i], 0.f) * gs;
}

// ---------------- fused epilogue: LN -> relu -> +x -> LN ----------------
__global__ void k_final(const float* __restrict__ x,
                        const float* __restrict__ fus_g, const float* __restrict__ fus_beta,
                        const float* __restrict__ norm_g, const float* __restrict__ norm_b,
                        float* __restrict__ out, int N) {
    int warp = (blockIdx.x * blockDim.x + threadIdx.x) >> 5;
    int lane = threadIdx.x & 31;
    if (warp >= N) return;
    int n = warp;
    float4 z4 = *(const float4*)(g_fpre + (size_t)n * D_ + (lane << 2));
    float z[4] = {z4.x, z4.y, z4.z, z4.w};
    float s = z[0] + z[1] + z[2] + z[3];
    float q = z[0] * z[0] + z[1] * z[1] + z[2] * z[2] + z[3] * z[3];
    s = wredsum(s); q = wredsum(q);
    float mu = s * (1.f / 128.f);
    float var = q * (1.f / 128.f) - mu * mu;
    float inv = rsqrtf(var + 1e-5f);
    float4 x4 = *(const float4*)(x + (size_t)n * D_ + (lane << 2));
    float xa[4] = {x4.x, x4.y, x4.z, x4.w};
    float t[4];
    #pragma unroll
    for (int c = 0; c < 4; c++) {
        int d = (lane << 2) + c;
        float ln = (z[c] - mu) * inv * fus_g[d] + fus_beta[d];
        t[c] = xa[c] + fmaxf(ln, 0.f);
    }
    float s2 = t[0] + t[1] + t[2] + t[3];
    float q2 = t[0] * t[0] + t[1] * t[1] + t[2] * t[2] + t[3] * t[3];
    s2 = wredsum(s2); q2 = wredsum(q2);
    mu = s2 * (1.f / 128.f);
    var = q2 * (1.f / 128.f) - mu * mu;
    inv = rsqrtf(var + 1e-5f);
    float o[4];
    #pragma unroll
    for (int c = 0; c < 4; c++) {
        int d = (lane << 2) + c;
        o[c] = (t[c] - mu) * inv * norm_g[d] + norm_b[d];
    }
    *(float4*)(out + (size_t)n * D_ + (lane << 2)) = make_float4(o[0], o[1], o[2], o[3]);
}

// ---------------- host ----------------
extern "C" void kernel_launch(void* const* d_in, const int* in_sizes, int n_in,
                              void* d_out, int out_size) {
    const float* x        = (const float*)d_in[0];
    const int*   ei       = (const int*)d_in[1];
    const float* ea       = (const float*)d_in[2];
    const float* sage_Wl  = (const float*)d_in[3];
    const float* sage_Wr  = (const float*)d_in[4];
    const float* sage_b   = (const float*)d_in[5];
    const float* tq_W     = (const float*)d_in[6];
    const float* tq_b     = (const float*)d_in[7];
    const float* tk_W     = (const float*)d_in[8];
    const float* tk_b     = (const float*)d_in[9];
    const float* tv_W     = (const float*)d_in[10];
    const float* tv_b     = (const float*)d_in[11];
    const float* te_W     = (const float*)d_in[12];
    const float* tskip_W  = (const float*)d_in[13];
    const float* tskip_b  = (const float*)d_in[14];
    const float* gat_W    = (const float*)d_in[15];
    const float* att_src  = (const float*)d_in[16];
    const float* att_dst  = (const float*)d_in[17];
    const float* gat_bias = (const float*)d_in[18];
    const float* gate_s   = (const float*)d_in[19];
    const float* gate_a   = (const float*)d_in[20];
    const float* gate_n   = (const float*)d_in[21];
    const float* fus_W    = (const float*)d_in[22];
    const float* fus_b    = (const float*)d_in[23];
    const float* fus_g    = (const float*)d_in[24];
    const float* fus_beta = (const float*)d_in[25];
    const float* norm_g   = (const float*)d_in[26];
    const float* norm_b   = (const float*)d_in[27];

    int N = in_sizes[0] / D_;
    int E = in_sizes[1] / 2;
    const int* src = ei;
    const int* dst = ei + E;

    static float *pq = nullptr, *pk, *pv, *pg, *pxsr, *pskip, *pmean, *psWl, *pfpre, *pxcat;
    if (!pq) {
        cudaGetSymbolAddress((void**)&pq,    g_q);
        cudaGetSymbolAddress((void**)&pk,    g_k);
        cudaGetSymbolAddress((void**)&pv,    g_v);
        cudaGetSymbolAddress((void**)&pg,    g_g);
        cudaGetSymbolAddress((void**)&pxsr,  g_xsr);
        cudaGetSymbolAddress((void**)&pskip, g_skip);
        cudaGetSymbolAddress((void**)&pmean, g_mean);
        cudaGetSymbolAddress((void**)&psWl,  g_sWl);
        cudaGetSymbolAddress((void**)&pfpre, g_fpre);
        cudaGetSymbolAddress((void**)&pxcat, g_xcat);
    }

    // CSR by destination
    k_zero<<<(N + 255) / 256, 256>>>(N);
    k_count<<<(E + 255) / 256, 256>>>(dst, E);
    k_scan<<<1, 1024>>>(N);
    k_fill<<<(E + 255) / 256, 256>>>(dst, E);

    dim3 g512(HD_ / 64, (N + 63) / 64);
    dim3 g128(D_ / 64, (N + 63) / 64);

    // projections
    sgemm<<<g512, 256>>>(x, tq_W, tq_b, pq, N, HD_, D_);
    sgemm<<<g512, 256>>>(x, tk_W, tk_b, pk, N, HD_, D_);
    sgemm<<<g512, 256>>>(x, tv_W, tv_b, pv, N, HD_, D_);
    sgemm<<<g512, 256>>>(x, gat_W, nullptr, pg, N, HD_, D_);
    sgemm<<<g128, 256>>>(x, sage_Wr, nullptr, pxsr, N, D_, D_);
    sgemm<<<g128, 256>>>(x, tskip_W, tskip_b, pskip, N, D_, D_);

    // edge phases (gather, warp per node)
    int nb = (N + 7) / 8;
    k_asad<<<nb, 256>>>(att_src, att_dst, N);
    k_trans_sage<<<nb, 256>>>(src, ea, te_W, x, gate_a, N);
    k_gat<<<nb, 256>>>(src, gat_bias, gate_n, N);

    // SAGE linear on mean, then short branch write
    sgemm<<<g128, 256>>>(pmean, sage_Wl, sage_b, psWl, N, D_, D_);
    k_short<<<(N * D_ + 255) / 256, 256>>>(gate_s, N);

    // fusion GEMM + epilogue
    sgemm<<<g128, 256>>>(pxcat, fus_W, fus_b, pfpre, N, D_, 3 * D_);
    k_final<<<nb, 256>>>(x, fus_g, fus_beta, norm_g, norm_b, (float*)d_out, N);
}

// round 8
// speedup vs baseline: 1.2524x; 1.2524x over previous
#include <cuda_runtime.h>
#include <math.h>
#include <stdint.h>

#define D_   128
#define H_   4
#define HD_  512
#define ED_  16
#define MAXN 50000
#define MAXE 150000

// ---------------- scratch (device globals; no allocations allowed) ----------------
__device__ float g_q[(size_t)MAXN * HD_];
__device__ float g_k[(size_t)MAXN * HD_];
__device__ float g_v[(size_t)MAXN * HD_];
__device__ float g_g[(size_t)MAXN * HD_];
__device__ float g_xsr[(size_t)MAXN * D_];
__device__ float g_skip[(size_t)MAXN * D_];
__device__ float g_mean[(size_t)MAXN * D_];
__device__ float g_sWl[(size_t)MAXN * D_];
__device__ float g_fpre[(size_t)MAXN * D_];
__device__ float g_xcat[(size_t)MAXN * 3 * D_];
__device__ float g_as[MAXN * H_];
__device__ float g_ad[MAXN * H_];
__device__ int   g_deg[MAXN];
__device__ int   g_cur[MAXN];
__device__ int   g_rowptr[MAXN + 1];
__device__ int   g_eidx[MAXE];
// transposed tf32-rounded weights
__device__ float g_wt[4 * HD_ * D_ + 3 * D_ * D_ + D_ * 3 * D_];

#define WT_Q    0
#define WT_K    (HD_ * D_)
#define WT_V    (2 * HD_ * D_)
#define WT_G    (3 * HD_ * D_)
#define WT_WR   (4 * HD_ * D_)
#define WT_SKIP (4 * HD_ * D_ + D_ * D_)
#define WT_WL   (4 * HD_ * D_ + 2 * D_ * D_)
#define WT_FUS  (4 * HD_ * D_ + 3 * D_ * D_)

__device__ __forceinline__ uint32_t f2tf32(float v) {
    uint32_t r;
    asm("cvt.rna.tf32.f32 %0, %1;" : "=r"(r) : "f"(v));
    return r;
}

__device__ __forceinline__ float wredsum(float v) {
    v += __shfl_xor_sync(0xffffffffu, v, 16);
    v += __shfl_xor_sync(0xffffffffu, v, 8);
    v += __shfl_xor_sync(0xffffffffu, v, 4);
    v += __shfl_xor_sync(0xffffffffu, v, 2);
    v += __shfl_xor_sync(0xffffffffu, v, 1);
    return v;
}
__device__ __forceinline__ float lrelu02(float x) { return x > 0.f ? x : 0.2f * x; }
__device__ __forceinline__ float sigm(float x) { return 1.f / (1.f + __expf(-x)); }

// ---------------- weight transpose + tf32 round: W[K][Nc] -> Wt[Nc][K] ----------------
__global__ void k_transpose(const float* __restrict__ W, float* __restrict__ Wt, int K, int Nc) {
    int i = blockIdx.x * blockDim.x + threadIdx.x;
    if (i < K * Nc) {
        int k = i / Nc, n = i % Nc;
        ((uint32_t*)Wt)[(size_t)n * K + k] = f2tf32(W[i]);
    }
}

// ---------------- mma.sync tf32 GEMM: C[M,Nc] = A[M,K] @ Bt^T (+bias) ----------------
// BM=BN=128, BK=32, 256 threads = 8 warps (2x4), warp tile 64x32.
// smem: As[k][m], Bs[k][n], pitch 136 words -> conflict-free STS and frag LDS.
#define PITCH 136

__global__ void __launch_bounds__(256)
mma_gemm(const float* __restrict__ A, const float* __restrict__ Bt,
         const float* __restrict__ bias, float* __restrict__ C,
         int M, int Nc, int K) {
    __shared__ float As[32][PITCH];
    __shared__ float Bs[32][PITCH];
    int tid = threadIdx.x, wid = tid >> 5, lane = tid & 31;
    int rowStart = blockIdx.y * 128, colStart = blockIdx.x * 128;
    int warp_m = (wid >> 2) * 64;   // 0 or 64
    int warp_n = (wid & 3) * 32;    // 0,32,64,96
    int gq = lane >> 2;             // groupID
    int tg = lane & 3;              // thread-in-group

    float acc[4][4][4];
    #pragma unroll
    for (int mt = 0; mt < 4; mt++)
        #pragma unroll
        for (int nt = 0; nt < 4; nt++)
            #pragma unroll
            for (int c = 0; c < 4; c++) acc[mt][nt][c] = 0.f;

    int lrow = tid & 127;            // row loaded by this thread (A: m, B: n)
    int kqBase = (tid >> 7) * 4;     // float4 index base (0 or 4)
    int gr = rowStart + lrow;

    for (int k0 = 0; k0 < K; k0 += 32) {
        // load A tile (row-strided float4 per lane), tf32-round, store transposed
        #pragma unroll
        for (int i = 0; i < 4; i++) {
            int kq = kqBase + i;
            float4 av = make_float4(0.f, 0.f, 0.f, 0.f);
            if (gr < M) av = *(const float4*)(A + (size_t)gr * K + k0 + (kq << 2));
            As[(kq << 2) + 0][lrow] = __uint_as_float(f2tf32(av.x));
            As[(kq << 2) + 1][lrow] = __uint_as_float(f2tf32(av.y));
            As[(kq << 2) + 2][lrow] = __uint_as_float(f2tf32(av.z));
            As[(kq << 2) + 3][lrow] = __uint_as_float(f2tf32(av.w));
        }
        // load B tile (weights pre-rounded tf32)
        #pragma unroll
        for (int i = 0; i < 4; i++) {
            int kq = kqBase + i;
            float4 bv = *(const float4*)(Bt + (size_t)(colStart + lrow) * K + k0 + (kq << 2));
            Bs[(kq << 2) + 0][lrow] = bv.x;
            Bs[(kq << 2) + 1][lrow] = bv.y;
            Bs[(kq << 2) + 2][lrow] = bv.z;
            Bs[(kq << 2) + 3][lrow] = bv.w;
        }
        __syncthreads();

        #pragma unroll
        for (int kk = 0; kk < 4; kk++) {
            int kb = kk << 3;
            uint32_t a[4][4], b[4][2];
            #pragma unroll
            for (int mt = 0; mt < 4; mt++) {
                int m0 = warp_m + mt * 16 + gq;
                a[mt][0] = __float_as_uint(As[kb + tg][m0]);
                a[mt][1] = __float_as_uint(As[kb + tg][m0 + 8]);
                a[mt][2] = __float_as_uint(As[kb + tg + 4][m0]);
                a[mt][3] = __float_as_uint(As[kb + tg + 4][m0 + 8]);
            }
            #pragma unroll
            for (int nt = 0; nt < 4; nt++) {
                int n0 = warp_n + nt * 8 + gq;
                b[nt][0] = __float_as_uint(Bs[kb + tg][n0]);
                b[nt][1] = __float_as_uint(Bs[kb + tg + 4][n0]);
            }
            #pragma unroll
            for (int mt = 0; mt < 4; mt++)
                #pragma unroll
                for (int nt = 0; nt < 4; nt++) {
                    asm volatile(
                        "mma.sync.aligned.m16n8k8.row.col.f32.tf32.tf32.f32 "
                        "{%0,%1,%2,%3}, {%4,%5,%6,%7}, {%8,%9}, {%0,%1,%2,%3};"
                        : "+f"(acc[mt][nt][0]), "+f"(acc[mt][nt][1]),
                          "+f"(acc[mt][nt][2]), "+f"(acc[mt][nt][3])
                        : "r"(a[mt][0]), "r"(a[mt][1]), "r"(a[mt][2]), "r"(a[mt][3]),
                          "r"(b[nt][0]), "r"(b[nt][1]));
                }
        }
        __syncthreads();
    }

    // epilogue
    #pragma unroll
    for (int mt = 0; mt < 4; mt++) {
        int r0 = rowStart + warp_m + mt * 16 + gq;
        #pragma unroll
        for (int nt = 0; nt < 4; nt++) {
            int cb = colStart + warp_n + nt * 8 + tg * 2;
            float b0 = bias ? bias[cb] : 0.f;
            float b1 = bias ? bias[cb + 1] : 0.f;
            if (r0 < M) {
                C[(size_t)r0 * Nc + cb]     = acc[mt][nt][0] + b0;
                C[(size_t)r0 * Nc + cb + 1] = acc[mt][nt][1] + b1;
            }
            if (r0 + 8 < M) {
                C[(size_t)(r0 + 8) * Nc + cb]     = acc[mt][nt][2] + b0;
                C[(size_t)(r0 + 8) * Nc + cb + 1] = acc[mt][nt][3] + b1;
            }
        }
    }
}

// ---------------- CSR build ----------------
__global__ void k_zero(int N) {
    int i = blockIdx.x * blockDim.x + threadIdx.x;
    if (i < N) { g_deg[i] = 0; g_cur[i] = 0; }
}
__global__ void k_count(const int* __restrict__ dst, int E) {
    int e = blockIdx.x * blockDim.x + threadIdx.x;
    if (e < E) atomicAdd(&g_deg[dst[e]], 1);
}
__global__ void k_scan(int N) {
    __shared__ int wsum[32];
    __shared__ int carry;
    int tid = threadIdx.x, lane = tid & 31, wid = tid >> 5;
    if (tid == 0) carry = 0;
    __syncthreads();
    for (int base = 0; base < N; base += 1024) {
        int i = base + tid;
        int v = (i < N) ? g_deg[i] : 0;
        int x = v;
        #pragma unroll
        for (int o = 1; o < 32; o <<= 1) {
            int y = __shfl_up_sync(0xffffffffu, x, o);
            if (lane >= o) x += y;
        }
        if (lane == 31) wsum[wid] = x;
        __syncthreads();
        if (wid == 0) {
            int wv = wsum[lane];
            #pragma unroll
            for (int o = 1; o < 32; o <<= 1) {
                int y = __shfl_up_sync(0xffffffffu, wv, o);
                if (lane >= o) wv += y;
            }
            wsum[lane] = wv;
        }
        __syncthreads();
        int woff = (wid > 0) ? wsum[wid - 1] : 0;
        int excl = x - v + woff;
        int c = carry;
        if (i < N) g_rowptr[i] = c + excl;
        int total = wsum[31];
        __syncthreads();
        if (tid == 0) carry = c + total;
        __syncthreads();
    }
    if (threadIdx.x == 0) g_rowptr[N] = carry;
}
__global__ void k_fill(const int* __restrict__ dst, int E) {
    int e = blockIdx.x * blockDim.x + threadIdx.x;
    if (e < E) {
        int d = dst[e];
        int p = atomicAdd(&g_cur[d], 1);
        g_eidx[g_rowptr[d] + p] = e;
    }
}

// ---------------- GAT attention coefficients ----------------
__global__ void k_asad(const float* __restrict__ att_src, const float* __restrict__ att_dst, int N) {
    __shared__ float aS[HD_], aD[HD_];
    for (int i = threadIdx.x; i < HD_; i += blockDim.x) { aS[i] = att_src[i]; aD[i] = att_dst[i]; }
    __syncthreads();
    int warp = (blockIdx.x * blockDim.x + threadIdx.x) >> 5;
    int lane = threadIdx.x & 31;
    if (warp >= N) return;
    int n = warp;
    float ps[4] = {0, 0, 0, 0}, pd[4] = {0, 0, 0, 0};
    #pragma unroll
    for (int t = 0; t < 16; t++) {
        float gv = g_g[(size_t)n * HD_ + lane + 32 * t];
        ps[t >> 2] = fmaf(gv, aS[lane + 32 * t], ps[t >> 2]);
        pd[t >> 2] = fmaf(gv, aD[lane + 32 * t], pd[t >> 2]);
    }
    float s0 = wredsum(ps[0]), s1 = wredsum(ps[1]), s2 = wredsum(ps[2]), s3 = wredsum(ps[3]);
    float d0 = wredsum(pd[0]), d1 = wredsum(pd[1]), d2 = wredsum(pd[2]), d3 = wredsum(pd[3]);
    if (lane == 0) {
        g_as[n * 4 + 0] = s0; g_as[n * 4 + 1] = s1; g_as[n * 4 + 2] = s2; g_as[n * 4 + 3] = s3;
        g_ad[n * 4 + 0] = d0; g_ad[n * 4 + 1] = d1; g_ad[n * 4 + 2] = d2; g_ad[n * 4 + 3] = d3;
    }
}

// ---------------- TransformerConv (online softmax) + SAGE mean, warp per dst node ----------------
__global__ void k_trans_sage(const int* __restrict__ src, const float* __restrict__ ea,
                             const float* __restrict__ te_W, const float* __restrict__ x,
                             const float* __restrict__ gate_attn, int N) {
    __shared__ float te_sm[ED_ * HD_];
    for (int i = threadIdx.x; i < ED_ * HD_; i += blockDim.x) te_sm[i] = te_W[i];
    __syncthreads();
    int warp = (blockIdx.x * blockDim.x + threadIdx.x) >> 5;
    int lane = threadIdx.x & 31;
    if (warp >= N) return;
    int n = warp;
    int r0 = g_rowptr[n], r1 = g_rowptr[n + 1];
    int deg = r1 - r0;

    float qreg[16], acc[16];
    #pragma unroll
    for (int t = 0; t < 16; t++) {
        qreg[t] = g_q[(size_t)n * HD_ + lane + 32 * t];
        acc[t] = 0.f;
    }
    float m0 = -INFINITY, m1 = -INFINITY, m2 = -INFINITY, m3 = -INFINITY;
    float s0 = 0.f, s1 = 0.f, s2 = 0.f, s3 = 0.f;
    float4 accx = make_float4(0.f, 0.f, 0.f, 0.f);
    const float scale = 0.08838834764831845f;

    for (int ei = r0; ei < r1; ei++) {
        int eid = g_eidx[ei];
        int s = src[eid];
        float4 xv = *(const float4*)(x + (size_t)s * D_ + (lane << 2));
        accx.x += xv.x; accx.y += xv.y; accx.z += xv.z; accx.w += xv.w;
        float eav = (lane < ED_) ? ea[(size_t)eid * ED_ + lane] : 0.f;
        float e[16];
        #pragma unroll
        for (int t = 0; t < 16; t++) e[t] = 0.f;
        #pragma unroll
        for (int j = 0; j < ED_; j++) {
            float a = __shfl_sync(0xffffffffu, eav, j);
            #pragma unroll
            for (int t = 0; t < 16; t++)
                e[t] = fmaf(a, te_sm[j * HD_ + lane + 32 * t], e[t]);
        }
        float p0 = 0.f, p1 = 0.f, p2 = 0.f, p3 = 0.f;
        #pragma unroll
        for (int t = 0; t < 16; t++) {
            float kv = g_k[(size_t)s * HD_ + lane + 32 * t] + e[t];
            float pr = qreg[t] * kv;
            if (t < 4) p0 += pr; else if (t < 8) p1 += pr; else if (t < 12) p2 += pr; else p3 += pr;
        }
        float l0 = wredsum(p0) * scale;
        float l1 = wredsum(p1) * scale;
        float l2 = wredsum(p2) * scale;
        float l3 = wredsum(p3) * scale;
        float n0 = fmaxf(m0, l0), sc0 = __expf(m0 - n0), w0 = __expf(l0 - n0);
        float n1 = fmaxf(m1, l1), sc1 = __expf(m1 - n1), w1 = __expf(l1 - n1);
        float n2 = fmaxf(m2, l2), sc2 = __expf(m2 - n2), w2 = __expf(l2 - n2);
        float n3 = fmaxf(m3, l3), sc3 = __expf(m3 - n3), w3 = __expf(l3 - n3);
        s0 = s0 * sc0 + w0; m0 = n0;
        s1 = s1 * sc1 + w1; m1 = n1;
        s2 = s2 * sc2 + w2; m2 = n2;
        s3 = s3 * sc3 + w3; m3 = n3;
        #pragma unroll
        for (int t = 0; t < 16; t++) {
            float vv = g_v[(size_t)s * HD_ + lane + 32 * t] + e[t];
            float sc = (t < 4) ? sc0 : (t < 8) ? sc1 : (t < 12) ? sc2 : sc3;
            float w  = (t < 4) ? w0  : (t < 8) ? w1  : (t < 12) ? w2  : w3;
            acc[t] = fmaf(acc[t], sc, w * vv);
        }
    }
    float ga = sigm(gate_attn[0]);
    float i0 = 1.f / (s0 + 1e-16f);
    float i1 = 1.f / (s1 + 1e-16f);
    float i2 = 1.f / (s2 + 1e-16f);
    float i3 = 1.f / (s3 + 1e-16f);
    #pragma unroll
    for (int t0 = 0; t0 < 4; t0++) {
        float od = 0.25f * (acc[t0] * i0 + acc[t0 + 4] * i1 + acc[t0 + 8] * i2 + acc[t0 + 12] * i3);
        int d = lane + 32 * t0;
        float val = fmaxf(od + g_skip[(size_t)n * D_ + d], 0.f) * ga;
        g_xcat[(size_t)n * 384 + 128 + d] = val;
    }
    float invd = 1.f / fmaxf((float)deg, 1.f);
    float4 mv = make_float4(accx.x * invd, accx.y * invd, accx.z * invd, accx.w * invd);
    *(float4*)(g_mean + (size_t)n * D_ + (lane << 2)) = mv;
}

// ---------------- GAT (self-loops + online softmax), warp per dst node ----------------
__global__ void k_gat(const int* __restrict__ src, const float* __restrict__ gat_bias,
                      const float* __restrict__ gate_nb, int N) {
    int warp = (blockIdx.x * blockDim.x + threadIdx.x) >> 5;
    int lane = threadIdx.x & 31;
    if (warp >= N) return;
    int n = warp;
    float ad0 = g_ad[n * 4 + 0], ad1 = g_ad[n * 4 + 1], ad2 = g_ad[n * 4 + 2], ad3 = g_ad[n * 4 + 3];
    float as0 = g_as[n * 4 + 0], as1 = g_as[n * 4 + 1], as2 = g_as[n * 4 + 2], as3 = g_as[n * 4 + 3];
    float m0 = lrelu02(as0 + ad0), m1 = lrelu02(as1 + ad1);
    float m2 = lrelu02(as2 + ad2), m3 = lrelu02(as3 + ad3);
    float s0 = 1.f, s1 = 1.f, s2 = 1.f, s3 = 1.f;
    float acc[16];
    #pragma unroll
    for (int t = 0; t < 16; t++) acc[t] = g_g[(size_t)n * HD_ + lane + 32 * t];
    int r0 = g_rowptr[n], r1 = g_rowptr[n + 1];
    for (int ei = r0; ei < r1; ei++) {
        int s = src[g_eidx[ei]];
        float l0 = lrelu02(g_as[s * 4 + 0] + ad0);
        float l1 = lrelu02(g_as[s * 4 + 1] + ad1);
        float l2 = lrelu02(g_as[s * 4 + 2] + ad2);
        float l3 = lrelu02(g_as[s * 4 + 3] + ad3);
        float n0 = fmaxf(m0, l0), sc0 = __expf(m0 - n0), w0 = __expf(l0 - n0);
        float n1 = fmaxf(m1, l1), sc1 = __expf(m1 - n1), w1 = __expf(l1 - n1);
        float n2 = fmaxf(m2, l2), sc2 = __expf(m2 - n2), w2 = __expf(l2 - n2);
        float n3 = fmaxf(m3, l3), sc3 = __expf(m3 - n3), w3 = __expf(l3 - n3);
        s0 = s0 * sc0 + w0; m0 = n0;
        s1 = s1 * sc1 + w1; m1 = n1;
        s2 = s2 * sc2 + w2; m2 = n2;
        s3 = s3 * sc3 + w3; m3 = n3;
        #pragma unroll
        for (int t = 0; t < 16; t++) {
            float sc = (t < 4) ? sc0 : (t < 8) ? sc1 : (t < 12) ? sc2 : sc3;
            float w  = (t < 4) ? w0  : (t < 8) ? w1  : (t < 12) ? w2  : w3;
            acc[t] = fmaf(acc[t], sc, w * g_g[(size_t)s * HD_ + lane + 32 * t]);
        }
    }
    float gn = sigm(gate_nb[0]);
    float i0 = 1.f / (s0 + 1e-16f);
    float i1 = 1.f / (s1 + 1e-16f);
    float i2 = 1.f / (s2 + 1e-16f);
    float i3 = 1.f / (s3 + 1e-16f);
    #pragma unroll
    for (int t0 = 0; t0 < 4; t0++) {
        float od = 0.25f * (acc[t0] * i0 + acc[t0 + 4] * i1 + acc[t0 + 8] * i2 + acc[t0 + 12] * i3);
        int d = lane + 32 * t0;
        float val = fmaxf(od + gat_bias[d], 0.f) * gn;
        g_xcat[(size_t)n * 384 + 256 + d] = val;
    }
}

// ---------------- short branch ----------------
__global__ void k_short(const float* __restrict__ gate_short, int N) {
    int i = blockIdx.x * blockDim.x + threadIdx.x;
    if (i >= N * D_) return;
    float gs = sigm(gate_short[0]);
    int n = i >> 7, d = i & 127;
    g_xcat[(size_t)n * 384 + d] = fmaxf(g_sWl[i] + g_xsr[i], 0.f) * gs;
}

// ---------------- fused epilogue: LN -> relu -> +x -> LN ----------------
__global__ void k_final(const float* __restrict__ x,
                        const float* __restrict__ fus_g, const float* __restrict__ fus_beta,
                        const float* __restrict__ norm_g, const float* __restrict__ norm_b,
                        float* __restrict__ out, int N) {
    int warp = (blockIdx.x * blockDim.x + threadIdx.x) >> 5;
    int lane = threadIdx.x & 31;
    if (warp >= N) return;
    int n = warp;
    float4 z4 = *(const float4*)(g_fpre + (size_t)n * D_ + (lane << 2));
    float z[4] = {z4.x, z4.y, z4.z, z4.w};
    float s = z[0] + z[1] + z[2] + z[3];
    float q = z[0] * z[0] + z[1] * z[1] + z[2] * z[2] + z[3] * z[3];
    s = wredsum(s); q = wredsum(q);
    float mu = s * (1.f / 128.f);
    float var = q * (1.f / 128.f) - mu * mu;
    float inv = rsqrtf(var + 1e-5f);
    float4 x4 = *(const float4*)(x + (size_t)n * D_ + (lane << 2));
    float xa[4] = {x4.x, x4.y, x4.z, x4.w};
    float t[4];
    #pragma unroll
    for (int c = 0; c < 4; c++) {
        int d = (lane << 2) + c;
        float ln = (z[c] - mu) * inv * fus_g[d] + fus_beta[d];
        t[c] = xa[c] + fmaxf(ln, 0.f);
    }
    float s2 = t[0] + t[1] + t[2] + t[3];
    float q2 = t[0] * t[0] + t[1] * t[1] + t[2] * t[2] + t[3] * t[3];
    s2 = wredsum(s2); q2 = wredsum(q2);
    mu = s2 * (1.f / 128.f);
    var = q2 * (1.f / 128.f) - mu * mu;
    inv = rsqrtf(var + 1e-5f);
    float o[4];
    #pragma unroll
    for (int c = 0; c < 4; c++) {
        int d = (lane << 2) + c;
        o[c] = (t[c] - mu) * inv * norm_g[d] + norm_b[d];
    }
    *(float4*)(out + (size_t)n * D_ + (lane << 2)) = make_float4(o[0], o[1], o[2], o[3]);
}

// ---------------- host ----------------
extern "C" void kernel_launch(void* const* d_in, const int* in_sizes, int n_in,
                              void* d_out, int out_size) {
    const float* x        = (const float*)d_in[0];
    const int*   ei       = (const int*)d_in[1];
    const float* ea       = (const float*)d_in[2];
    const float* sage_Wl  = (const float*)d_in[3];
    const float* sage_Wr  = (const float*)d_in[4];
    const float* sage_b   = (const float*)d_in[5];
    const float* tq_W     = (const float*)d_in[6];
    const float* tq_b     = (const float*)d_in[7];
    const float* tk_W     = (const float*)d_in[8];
    const float* tk_b     = (const float*)d_in[9];
    const float* tv_W     = (const float*)d_in[10];
    const float* tv_b     = (const float*)d_in[11];
    const float* te_W     = (const float*)d_in[12];
    const float* tskip_W  = (const float*)d_in[13];
    const float* tskip_b  = (const float*)d_in[14];
    const float* gat_W    = (const float*)d_in[15];
    const float* att_src  = (const float*)d_in[16];
    const float* att_dst  = (const float*)d_in[17];
    const float* gat_bias = (const float*)d_in[18];
    const float* gate_s   = (const float*)d_in[19];
    const float* gate_a   = (const float*)d_in[20];
    const float* gate_n   = (const float*)d_in[21];
    const float* fus_W    = (const float*)d_in[22];
    const float* fus_b    = (const float*)d_in[23];
    const float* fus_g    = (const float*)d_in[24];
    const float* fus_beta = (const float*)d_in[25];
    const float* norm_g   = (const float*)d_in[26];
    const float* norm_b   = (const float*)d_in[27];

    int N = in_sizes[0] / D_;
    int E = in_sizes[1] / 2;
    const int* src = ei;
    const int* dst = ei + E;

    static float *pq = nullptr, *pk, *pv, *pg, *pxsr, *pskip, *pmean, *psWl, *pfpre, *pxcat, *pwt;
    if (!pq) {
        cudaGetSymbolAddress((void**)&pq,    g_q);
        cudaGetSymbolAddress((void**)&pk,    g_k);
        cudaGetSymbolAddress((void**)&pv,    g_v);
        cudaGetSymbolAddress((void**)&pg,    g_g);
        cudaGetSymbolAddress((void**)&pxsr,  g_xsr);
        cudaGetSymbolAddress((void**)&pskip, g_skip);
        cudaGetSymbolAddress((void**)&pmean, g_mean);
        cudaGetSymbolAddress((void**)&psWl,  g_sWl);
        cudaGetSymbolAddress((void**)&pfpre, g_fpre);
        cudaGetSymbolAddress((void**)&pxcat, g_xcat);
        cudaGetSymbolAddress((void**)&pwt,   g_wt);
    }

    // CSR by destination
    k_zero<<<(N + 255) / 256, 256>>>(N);
    k_count<<<(E + 255) / 256, 256>>>(dst, E);
    k_scan<<<1, 1024>>>(N);
    k_fill<<<(E + 255) / 256, 256>>>(dst, E);

    // weight transposes + tf32 rounding
    int tb = 256;
    k_transpose<<<(D_ * HD_ + tb - 1) / tb, tb>>>(tq_W,    pwt + WT_Q,    D_, HD_);
    k_transpose<<<(D_ * HD_ + tb - 1) / tb, tb>>>(tk_W,    pwt + WT_K,    D_, HD_);
    k_transpose<<<(D_ * HD_ + tb - 1) / tb, tb>>>(tv_W,    pwt + WT_V,    D_, HD_);
    k_transpose<<<(D_ * HD_ + tb - 1) / tb, tb>>>(gat_W,   pwt + WT_G,    D_, HD_);
    k_transpose<<<(D_ * D_ + tb - 1) / tb, tb>>>(sage_Wr,  pwt + WT_WR,   D_, D_);
    k_transpose<<<(D_ * D_ + tb - 1) / tb, tb>>>(tskip_W,  pwt + WT_SKIP, D_, D_);
    k_transpose<<<(D_ * D_ + tb - 1) / tb, tb>>>(sage_Wl,  pwt + WT_WL,   D_, D_);
    k_transpose<<<(3 * D_ * D_ + tb - 1) / tb, tb>>>(fus_W, pwt + WT_FUS, 3 * D_, D_);

    int mt = (N + 127) / 128;
    dim3 g512(HD_ / 128, mt);
    dim3 g128(1, mt);

    // projections on tensor cores (mma.sync tf32)
    mma_gemm<<<g512, 256>>>(x, pwt + WT_Q,  tq_b,   pq,    N, HD_, D_);
    mma_gemm<<<g512, 256>>>(x, pwt + WT_K,  tk_b,   pk,    N, HD_, D_);
    mma_gemm<<<g512, 256>>>(x, pwt + WT_V,  tv_b,   pv,    N, HD_, D_);
    mma_gemm<<<g512, 256>>>(x, pwt + WT_G,  nullptr, pg,   N, HD_, D_);
    mma_gemm<<<g128, 256>>>(x, pwt + WT_WR, nullptr, pxsr, N, D_, D_);
    mma_gemm<<<g128, 256>>>(x, pwt + WT_SKIP, tskip_b, pskip, N, D_, D_);

    // edge phases (gather, warp per node)
    int nb = (N + 7) / 8;
    k_asad<<<nb, 256>>>(att_src, att_dst, N);
    k_trans_sage<<<nb, 256>>>(src, ea, te_W, x, gate_a, N);
    k_gat<<<nb, 256>>>(src, gat_bias, gate_n, N);

    // SAGE linear on mean, then short branch write
    mma_gemm<<<g128, 256>>>(pmean, pwt + WT_WL, sage_b, psWl, N, D_, D_);
    k_short<<<(N * D_ + 255) / 256, 256>>>(gate_s, N);

    // fusion GEMM (K=384) + epilogue
    mma_gemm<<<g128, 256>>>(pxcat, pwt + WT_FUS, fus_b, pfpre, N, D_, 3 * D_);
    k_final<<<nb, 256>>>(x, fus_g, fus_beta, norm_g, norm_b, (float*)d_out, N);
}

// round 9
// speedup vs baseline: 1.3497x; 1.0777x over previous
#include <cuda_runtime.h>
#include <math.h>
#include <stdint.h>

#define D_   128
#define H_   4
#define HD_  512
#define ED_  16
#define MAXN 50000
#define MAXE 150000

// ---------------- scratch (device globals; no allocations allowed) ----------------
__device__ float g_q[(size_t)MAXN * HD_];
__device__ float g_k[(size_t)MAXN * HD_];
__device__ float g_v[(size_t)MAXN * HD_];
__device__ float g_g[(size_t)MAXN * HD_];
__device__ float g_xsr[(size_t)MAXN * D_];
__device__ float g_skip[(size_t)MAXN * D_];
__device__ float g_mean[(size_t)MAXN * D_];
__device__ float g_sWl[(size_t)MAXN * D_];
__device__ float g_fpre[(size_t)MAXN * D_];
__device__ float g_xcat[(size_t)MAXN * 3 * D_];
__device__ float g_as[MAXN * H_];
__device__ float g_ad[MAXN * H_];
__device__ int   g_deg[MAXN];
__device__ int   g_cur[MAXN];
__device__ int   g_rowptr[MAXN + 1];
__device__ int   g_eidx[MAXE];
// transposed tf32-rounded weights
__device__ float g_wt[4 * HD_ * D_ + 3 * D_ * D_ + D_ * 3 * D_];

#define WT_Q    0
#define WT_K    (HD_ * D_)
#define WT_V    (2 * HD_ * D_)
#define WT_G    (3 * HD_ * D_)
#define WT_WR   (4 * HD_ * D_)
#define WT_SKIP (4 * HD_ * D_ + D_ * D_)
#define WT_WL   (4 * HD_ * D_ + 2 * D_ * D_)
#define WT_FUS  (4 * HD_ * D_ + 3 * D_ * D_)

__device__ __forceinline__ uint32_t f2tf32(float v) {
    uint32_t r;
    asm("cvt.rna.tf32.f32 %0, %1;" : "=r"(r) : "f"(v));
    return r;
}

__device__ __forceinline__ float wredsum(float v) {
    v += __shfl_xor_sync(0xffffffffu, v, 16);
    v += __shfl_xor_sync(0xffffffffu, v, 8);
    v += __shfl_xor_sync(0xffffffffu, v, 4);
    v += __shfl_xor_sync(0xffffffffu, v, 2);
    v += __shfl_xor_sync(0xffffffffu, v, 1);
    return v;
}
__device__ __forceinline__ float lrelu02(float x) { return x > 0.f ? x : 0.2f * x; }
__device__ __forceinline__ float sigm(float x) { return 1.f / (1.f + __expf(-x)); }

// ---------------- weight transpose + tf32 round: W[K][Nc] -> Wt[Nc][K] ----------------
__global__ void k_transpose(const float* __restrict__ W, float* __restrict__ Wt, int K, int Nc) {
    int i = blockIdx.x * blockDim.x + threadIdx.x;
    if (i < K * Nc) {
        int k = i / Nc, n = i % Nc;
        ((uint32_t*)Wt)[(size_t)n * K + k] = f2tf32(W[i]);
    }
}

// ---------------- mma.sync tf32 GEMM: C[M,Nc] = A[M,K] @ Bt^T (+bias) ----------------
#define PITCH 136

__global__ void __launch_bounds__(256)
mma_gemm(const float* __restrict__ A, const float* __restrict__ Bt,
         const float* __restrict__ bias, float* __restrict__ C,
         int M, int Nc, int K) {
    __shared__ float As[32][PITCH];
    __shared__ float Bs[32][PITCH];
    int tid = threadIdx.x, wid = tid >> 5, lane = tid & 31;
    int rowStart = blockIdx.y * 128, colStart = blockIdx.x * 128;
    int warp_m = (wid >> 2) * 64;
    int warp_n = (wid & 3) * 32;
    int gq = lane >> 2;
    int tg = lane & 3;

    float acc[4][4][4];
    #pragma unroll
    for (int mt = 0; mt < 4; mt++)
        #pragma unroll
        for (int nt = 0; nt < 4; nt++)
            #pragma unroll
            for (int c = 0; c < 4; c++) acc[mt][nt][c] = 0.f;

    int lrow = tid & 127;
    int kqBase = (tid >> 7) * 4;
    int gr = rowStart + lrow;

    for (int k0 = 0; k0 < K; k0 += 32) {
        #pragma unroll
        for (int i = 0; i < 4; i++) {
            int kq = kqBase + i;
            float4 av = make_float4(0.f, 0.f, 0.f, 0.f);
            if (gr < M) av = *(const float4*)(A + (size_t)gr * K + k0 + (kq << 2));
            As[(kq << 2) + 0][lrow] = __uint_as_float(f2tf32(av.x));
            As[(kq << 2) + 1][lrow] = __uint_as_float(f2tf32(av.y));
            As[(kq << 2) + 2][lrow] = __uint_as_float(f2tf32(av.z));
            As[(kq << 2) + 3][lrow] = __uint_as_float(f2tf32(av.w));
        }
        #pragma unroll
        for (int i = 0; i < 4; i++) {
            int kq = kqBase + i;
            float4 bv = *(const float4*)(Bt + (size_t)(colStart + lrow) * K + k0 + (kq << 2));
            Bs[(kq << 2) + 0][lrow] = bv.x;
            Bs[(kq << 2) + 1][lrow] = bv.y;
            Bs[(kq << 2) + 2][lrow] = bv.z;
            Bs[(kq << 2) + 3][lrow] = bv.w;
        }
        __syncthreads();

        #pragma unroll
        for (int kk = 0; kk < 4; kk++) {
            int kb = kk << 3;
            uint32_t a[4][4], b[4][2];
            #pragma unroll
            for (int mt = 0; mt < 4; mt++) {
                int m0 = warp_m + mt * 16 + gq;
                a[mt][0] = __float_as_uint(As[kb + tg][m0]);
                a[mt][1] = __float_as_uint(As[kb + tg][m0 + 8]);
                a[mt][2] = __float_as_uint(As[kb + tg + 4][m0]);
                a[mt][3] = __float_as_uint(As[kb + tg + 4][m0 + 8]);
            }
            #pragma unroll
            for (int nt = 0; nt < 4; nt++) {
                int n0 = warp_n + nt * 8 + gq;
                b[nt][0] = __float_as_uint(Bs[kb + tg][n0]);
                b[nt][1] = __float_as_uint(Bs[kb + tg + 4][n0]);
            }
            #pragma unroll
            for (int mt = 0; mt < 4; mt++)
                #pragma unroll
                for (int nt = 0; nt < 4; nt++) {
                    asm volatile(
                        "mma.sync.aligned.m16n8k8.row.col.f32.tf32.tf32.f32 "
                        "{%0,%1,%2,%3}, {%4,%5,%6,%7}, {%8,%9}, {%0,%1,%2,%3};"
                        : "+f"(acc[mt][nt][0]), "+f"(acc[mt][nt][1]),
                          "+f"(acc[mt][nt][2]), "+f"(acc[mt][nt][3])
                        : "r"(a[mt][0]), "r"(a[mt][1]), "r"(a[mt][2]), "r"(a[mt][3]),
                          "r"(b[nt][0]), "r"(b[nt][1]));
                }
        }
        __syncthreads();
    }

    #pragma unroll
    for (int mt = 0; mt < 4; mt++) {
        int r0 = rowStart + warp_m + mt * 16 + gq;
        #pragma unroll
        for (int nt = 0; nt < 4; nt++) {
            int cb = colStart + warp_n + nt * 8 + tg * 2;
            float b0 = bias ? bias[cb] : 0.f;
            float b1 = bias ? bias[cb + 1] : 0.f;
            if (r0 < M) {
                C[(size_t)r0 * Nc + cb]     = acc[mt][nt][0] + b0;
                C[(size_t)r0 * Nc + cb + 1] = acc[mt][nt][1] + b1;
            }
            if (r0 + 8 < M) {
                C[(size_t)(r0 + 8) * Nc + cb]     = acc[mt][nt][2] + b0;
                C[(size_t)(r0 + 8) * Nc + cb + 1] = acc[mt][nt][3] + b1;
            }
        }
    }
}

// ---------------- CSR build ----------------
__global__ void k_zero(int N) {
    int i = blockIdx.x * blockDim.x + threadIdx.x;
    if (i < N) { g_deg[i] = 0; g_cur[i] = 0; }
}
__global__ void k_count(const int* __restrict__ dst, int E) {
    int e = blockIdx.x * blockDim.x + threadIdx.x;
    if (e < E) atomicAdd(&g_deg[dst[e]], 1);
}
__global__ void k_scan(int N) {
    __shared__ int wsum[32];
    __shared__ int carry;
    int tid = threadIdx.x, lane = tid & 31, wid = tid >> 5;
    if (tid == 0) carry = 0;
    __syncthreads();
    for (int base = 0; base < N; base += 1024) {
        int i = base + tid;
        int v = (i < N) ? g_deg[i] : 0;
        int x = v;
        #pragma unroll
        for (int o = 1; o < 32; o <<= 1) {
            int y = __shfl_up_sync(0xffffffffu, x, o);
            if (lane >= o) x += y;
        }
        if (lane == 31) wsum[wid] = x;
        __syncthreads();
        if (wid == 0) {
            int wv = wsum[lane];
            #pragma unroll
            for (int o = 1; o < 32; o <<= 1) {
                int y = __shfl_up_sync(0xffffffffu, wv, o);
                if (lane >= o) wv += y;
            }
            wsum[lane] = wv;
        }
        __syncthreads();
        int woff = (wid > 0) ? wsum[wid - 1] : 0;
        int excl = x - v + woff;
        int c = carry;
        if (i < N) g_rowptr[i] = c + excl;
        int total = wsum[31];
        __syncthreads();
        if (tid == 0) carry = c + total;
        __syncthreads();
    }
    if (threadIdx.x == 0) g_rowptr[N] = carry;
}
__global__ void k_fill(const int* __restrict__ dst, int E) {
    int e = blockIdx.x * blockDim.x + threadIdx.x;
    if (e < E) {
        int d = dst[e];
        int p = atomicAdd(&g_cur[d], 1);
        g_eidx[g_rowptr[d] + p] = e;
    }
}

// ---------------- GAT attention coefficients ----------------
__global__ void k_asad(const float* __restrict__ att_src, const float* __restrict__ att_dst, int N) {
    __shared__ float aS[HD_], aD[HD_];
    for (int i = threadIdx.x; i < HD_; i += blockDim.x) { aS[i] = att_src[i]; aD[i] = att_dst[i]; }
    __syncthreads();
    int warp = (blockIdx.x * blockDim.x + threadIdx.x) >> 5;
    int lane = threadIdx.x & 31;
    if (warp >= N) return;
    int n = warp;
    float ps[4] = {0, 0, 0, 0}, pd[4] = {0, 0, 0, 0};
    #pragma unroll
    for (int t = 0; t < 16; t++) {
        float gv = g_g[(size_t)n * HD_ + lane + 32 * t];
        ps[t >> 2] = fmaf(gv, aS[lane + 32 * t], ps[t >> 2]);
        pd[t >> 2] = fmaf(gv, aD[lane + 32 * t], pd[t >> 2]);
    }
    float s0 = wredsum(ps[0]), s1 = wredsum(ps[1]), s2 = wredsum(ps[2]), s3 = wredsum(ps[3]);
    float d0 = wredsum(pd[0]), d1 = wredsum(pd[1]), d2 = wredsum(pd[2]), d3 = wredsum(pd[3]);
    if (lane == 0) {
        g_as[n * 4 + 0] = s0; g_as[n * 4 + 1] = s1; g_as[n * 4 + 2] = s2; g_as[n * 4 + 3] = s3;
        g_ad[n * 4 + 0] = d0; g_ad[n * 4 + 1] = d1; g_ad[n * 4 + 2] = d2; g_ad[n * 4 + 3] = d3;
    }
}

// ---------------- TransformerConv + SAGE mean: warp per (node, head) ----------------
// block = 256 threads = 8 warps = 2 nodes x 4 heads. N must be even (50000 ok, guarded anyway).
__global__ void __launch_bounds__(256)
k_trans_sage(const int* __restrict__ src, const float* __restrict__ ea,
             const float* __restrict__ te_W, const float* __restrict__ x,
             const float* __restrict__ gate_attn, int N) {
    __shared__ float4 te_sm[ED_][D_];        // te_W[j][:] as float4: 32 KB
    __shared__ float4 red[2][H_][32];        // per-node per-head normalized outputs: 4 KB
    for (int i = threadIdx.x; i < ED_ * D_; i += blockDim.x) {
        int j = i >> 7, c = i & 127;
        te_sm[j][c] = *(const float4*)(te_W + (size_t)j * HD_ + (c << 2));
    }
    __syncthreads();

    int w = threadIdx.x >> 5, lane = threadIdx.x & 31;
    int nl = w >> 2, head = w & 3;
    int n = blockIdx.x * 2 + nl;
    bool active = (n < N);
    const float scale = 0.08838834764831845f;  // 1/sqrt(128)

    float4 acc = make_float4(0.f, 0.f, 0.f, 0.f);
    float4 accx = make_float4(0.f, 0.f, 0.f, 0.f);
    float m = -INFINITY, ssum = 0.f;
    int deg = 0;

    if (active) {
        int c = head * 32 + lane;  // float4 index into 512-float row
        float4 q4 = ((const float4*)(g_q + (size_t)n * HD_))[c];
        int r0 = g_rowptr[n], r1 = g_rowptr[n + 1];
        deg = r1 - r0;
        for (int ei = r0; ei < r1; ei++) {
            int eid = g_eidx[ei];
            int s = src[eid];
            if (head == 0) {
                float4 xv = ((const float4*)(x + (size_t)s * D_))[lane];
                accx.x += xv.x; accx.y += xv.y; accx.z += xv.z; accx.w += xv.w;
            }
            float eav = (lane < ED_) ? ea[(size_t)eid * ED_ + lane] : 0.f;
            float4 e = make_float4(0.f, 0.f, 0.f, 0.f);
            #pragma unroll
            for (int j = 0; j < ED_; j++) {
                float a = __shfl_sync(0xffffffffu, eav, j);
                float4 t = te_sm[j][c];
                e.x = fmaf(a, t.x, e.x); e.y = fmaf(a, t.y, e.y);
                e.z = fmaf(a, t.z, e.z); e.w = fmaf(a, t.w, e.w);
            }
            float4 k4 = ((const float4*)(g_k + (size_t)s * HD_))[c];
            float p = q4.x * (k4.x + e.x) + q4.y * (k4.y + e.y)
                    + q4.z * (k4.z + e.z) + q4.w * (k4.w + e.w);
            float l = wredsum(p) * scale;
            float nm = fmaxf(m, l), sc = __expf(m - nm), wgt = __expf(l - nm);
            ssum = ssum * sc + wgt; m = nm;
            float4 v4 = ((const float4*)(g_v + (size_t)s * HD_))[c];
            acc.x = fmaf(acc.x, sc, wgt * (v4.x + e.x));
            acc.y = fmaf(acc.y, sc, wgt * (v4.y + e.y));
            acc.z = fmaf(acc.z, sc, wgt * (v4.z + e.z));
            acc.w = fmaf(acc.w, sc, wgt * (v4.w + e.w));
        }
        float inv = 1.f / (ssum + 1e-16f);
        red[nl][head][lane] = make_float4(acc.x * inv, acc.y * inv, acc.z * inv, acc.w * inv);
        if (head == 0) {
            float invd = 1.f / fmaxf((float)deg, 1.f);
            ((float4*)(g_mean + (size_t)n * D_))[lane] =
                make_float4(accx.x * invd, accx.y * invd, accx.z * invd, accx.w * invd);
        }
    }
    __syncthreads();
    if (active && head == 0) {
        float ga = sigm(gate_attn[0]);
        float4 a0 = red[nl][0][lane], a1 = red[nl][1][lane];
        float4 a2 = red[nl][2][lane], a3 = red[nl][3][lane];
        float4 sk = ((const float4*)(g_skip + (size_t)n * D_))[lane];
        float4 o;
        o.x = fmaxf(0.25f * (a0.x + a1.x + a2.x + a3.x) + sk.x, 0.f) * ga;
        o.y = fmaxf(0.25f * (a0.y + a1.y + a2.y + a3.y) + sk.y, 0.f) * ga;
        o.z = fmaxf(0.25f * (a0.z + a1.z + a2.z + a3.z) + sk.z, 0.f) * ga;
        o.w = fmaxf(0.25f * (a0.w + a1.w + a2.w + a3.w) + sk.w, 0.f) * ga;
        *(float4*)(g_xcat + (size_t)n * 384 + 128 + (lane << 2)) = o;
    }
}

// ---------------- GAT: warp per (node, head) ----------------
__global__ void __launch_bounds__(256)
k_gat(const int* __restrict__ src, const float* __restrict__ gat_bias,
      const float* __restrict__ gate_nb, int N) {
    __shared__ float4 red[2][H_][32];
    int w = threadIdx.x >> 5, lane = threadIdx.x & 31;
    int nl = w >> 2, head = w & 3;
    int n = blockIdx.x * 2 + nl;
    bool active = (n < N);

    if (active) {
        int c = head * 32 + lane;
        float ad = g_ad[n * 4 + head];
        float m = lrelu02(g_as[n * 4 + head] + ad);
        float ssum = 1.f;
        float4 acc = ((const float4*)(g_g + (size_t)n * HD_))[c];  // self-loop
        int r0 = g_rowptr[n], r1 = g_rowptr[n + 1];
        for (int ei = r0; ei < r1; ei++) {
            int s = src[g_eidx[ei]];
            float l = lrelu02(g_as[s * 4 + head] + ad);
            float nm = fmaxf(m, l), sc = __expf(m - nm), wgt = __expf(l - nm);
            ssum = ssum * sc + wgt; m = nm;
            float4 g4 = ((const float4*)(g_g + (size_t)s * HD_))[c];
            acc.x = fmaf(acc.x, sc, wgt * g4.x);
            acc.y = fmaf(acc.y, sc, wgt * g4.y);
            acc.z = fmaf(acc.z, sc, wgt * g4.z);
            acc.w = fmaf(acc.w, sc, wgt * g4.w);
        }
        float inv = 1.f / (ssum + 1e-16f);
        red[nl][head][lane] = make_float4(acc.x * inv, acc.y * inv, acc.z * inv, acc.w * inv);
    }
    __syncthreads();
    if (active && head == 0) {
        float gn = sigm(gate_nb[0]);
        float4 a0 = red[nl][0][lane], a1 = red[nl][1][lane];
        float4 a2 = red[nl][2][lane], a3 = red[nl][3][lane];
        int d = lane << 2;
        float4 o;
        o.x = fmaxf(0.25f * (a0.x + a1.x + a2.x + a3.x) + gat_bias[d + 0], 0.f) * gn;
        o.y = fmaxf(0.25f * (a0.y + a1.y + a2.y + a3.y) + gat_bias[d + 1], 0.f) * gn;
        o.z = fmaxf(0.25f * (a0.z + a1.z + a2.z + a3.z) + gat_bias[d + 2], 0.f) * gn;
        o.w = fmaxf(0.25f * (a0.w + a1.w + a2.w + a3.w) + gat_bias[d + 3], 0.f) * gn;
        *(float4*)(g_xcat + (size_t)n * 384 + 256 + d) = o;
    }
}

// ---------------- short branch ----------------
__global__ void k_short(const float* __restrict__ gate_short, int N) {
    int i = blockIdx.x * blockDim.x + threadIdx.x;
    if (i >= N * D_) return;
    float gs = sigm(gate_short[0]);
    int n = i >> 7, d = i & 127;
    g_xcat[(size_t)n * 384 + d] = fmaxf(g_sWl[i] + g_xsr[i], 0.f) * gs;
}

// ---------------- fused epilogue: LN -> relu -> +x -> LN ----------------
__global__ void k_final(const float* __restrict__ x,
                        const float* __restrict__ fus_g, const float* __restrict__ fus_beta,
                        const float* __restrict__ norm_g, const float* __restrict__ norm_b,
                        float* __restrict__ out, int N) {
    int warp = (blockIdx.x * blockDim.x + threadIdx.x) >> 5;
    int lane = threadIdx.x & 31;
    if (warp >= N) return;
    int n = warp;
    float4 z4 = *(const float4*)(g_fpre + (size_t)n * D_ + (lane << 2));
    float z[4] = {z4.x, z4.y, z4.z, z4.w};
    float s = z[0] + z[1] + z[2] + z[3];
    float q = z[0] * z[0] + z[1] * z[1] + z[2] * z[2] + z[3] * z[3];
    s = wredsum(s); q = wredsum(q);
    float mu = s * (1.f / 128.f);
    float var = q * (1.f / 128.f) - mu * mu;
    float inv = rsqrtf(var + 1e-5f);
    float4 x4 = *(const float4*)(x + (size_t)n * D_ + (lane << 2));
    float xa[4] = {x4.x, x4.y, x4.z, x4.w};
    float t[4];
    #pragma unroll
    for (int c = 0; c < 4; c++) {
        int d = (lane << 2) + c;
        float ln = (z[c] - mu) * inv * fus_g[d] + fus_beta[d];
        t[c] = xa[c] + fmaxf(ln, 0.f);
    }
    float s2 = t[0] + t[1] + t[2] + t[3];
    float q2 = t[0] * t[0] + t[1] * t[1] + t[2] * t[2] + t[3] * t[3];
    s2 = wredsum(s2); q2 = wredsum(q2);
    mu = s2 * (1.f / 128.f);
    var = q2 * (1.f / 128.f) - mu * mu;
    inv = rsqrtf(var + 1e-5f);
    float o[4];
    #pragma unroll
    for (int c = 0; c < 4; c++) {
        int d = (lane << 2) + c;
        o[c] = (t[c] - mu) * inv * norm_g[d] + norm_b[d];
    }
    *(float4*)(out + (size_t)n * D_ + (lane << 2)) = make_float4(o[0], o[1], o[2], o[3]);
}

// ---------------- host ----------------
extern "C" void kernel_launch(void* const* d_in, const int* in_sizes, int n_in,
                              void* d_out, int out_size) {
    const float* x        = (const float*)d_in[0];
    const int*   ei       = (const int*)d_in[1];
    const float* ea       = (const float*)d_in[2];
    const float* sage_Wl  = (const float*)d_in[3];
    const float* sage_Wr  = (const float*)d_in[4];
    const float* sage_b   = (const float*)d_in[5];
    const float* tq_W     = (const float*)d_in[6];
    const float* tq_b     = (const float*)d_in[7];
    const float* tk_W     = (const float*)d_in[8];
    const float* tk_b     = (const float*)d_in[9];
    const float* tv_W     = (const float*)d_in[10];
    const float* tv_b     = (const float*)d_in[11];
    const float* te_W     = (const float*)d_in[12];
    const float* tskip_W  = (const float*)d_in[13];
    const float* tskip_b  = (const float*)d_in[14];
    const float* gat_W    = (const float*)d_in[15];
    const float* att_src  = (const float*)d_in[16];
    const float* att_dst  = (const float*)d_in[17];
    const float* gat_bias = (const float*)d_in[18];
    const float* gate_s   = (const float*)d_in[19];
    const float* gate_a   = (const float*)d_in[20];
    const float* gate_n   = (const float*)d_in[21];
    const float* fus_W    = (const float*)d_in[22];
    const float* fus_b    = (const float*)d_in[23];
    const float* fus_g    = (const float*)d_in[24];
    const float* fus_beta = (const float*)d_in[25];
    const float* norm_g   = (const float*)d_in[26];
    const float* norm_b   = (const float*)d_in[27];

    int N = in_sizes[0] / D_;
    int E = in_sizes[1] / 2;
    const int* src = ei;
    const int* dst = ei + E;

    static float *pq = nullptr, *pk, *pv, *pg, *pxsr, *pskip, *pmean, *psWl, *pfpre, *pxcat, *pwt;
    if (!pq) {
        cudaGetSymbolAddress((void**)&pq,    g_q);
        cudaGetSymbolAddress((void**)&pk,    g_k);
        cudaGetSymbolAddress((void**)&pv,    g_v);
        cudaGetSymbolAddress((void**)&pg,    g_g);
        cudaGetSymbolAddress((void**)&pxsr,  g_xsr);
        cudaGetSymbolAddress((void**)&pskip, g_skip);
        cudaGetSymbolAddress((void**)&pmean, g_mean);
        cudaGetSymbolAddress((void**)&psWl,  g_sWl);
        cudaGetSymbolAddress((void**)&pfpre, g_fpre);
        cudaGetSymbolAddress((void**)&pxcat, g_xcat);
        cudaGetSymbolAddress((void**)&pwt,   g_wt);
    }

    // CSR by destination
    k_zero<<<(N + 255) / 256, 256>>>(N);
    k_count<<<(E + 255) / 256, 256>>>(dst, E);
    k_scan<<<1, 1024>>>(N);
    k_fill<<<(E + 255) / 256, 256>>>(dst, E);

    // weight transposes + tf32 rounding
    int tb = 256;
    k_transpose<<<(D_ * HD_ + tb - 1) / tb, tb>>>(tq_W,    pwt + WT_Q,    D_, HD_);
    k_transpose<<<(D_ * HD_ + tb - 1) / tb, tb>>>(tk_W,    pwt + WT_K,    D_, HD_);
    k_transpose<<<(D_ * HD_ + tb - 1) / tb, tb>>>(tv_W,    pwt + WT_V,    D_, HD_);
    k_transpose<<<(D_ * HD_ + tb - 1) / tb, tb>>>(gat_W,   pwt + WT_G,    D_, HD_);
    k_transpose<<<(D_ * D_ + tb - 1) / tb, tb>>>(sage_Wr,  pwt + WT_WR,   D_, D_);
    k_transpose<<<(D_ * D_ + tb - 1) / tb, tb>>>(tskip_W,  pwt + WT_SKIP, D_, D_);
    k_transpose<<<(D_ * D_ + tb - 1) / tb, tb>>>(sage_Wl,  pwt + WT_WL,   D_, D_);
    k_transpose<<<(3 * D_ * D_ + tb - 1) / tb, tb>>>(fus_W, pwt + WT_FUS, 3 * D_, D_);

    int mt = (N + 127) / 128;
    dim3 g512(HD_ / 128, mt);
    dim3 g128(1, mt);

    // projections on tensor cores (mma.sync tf32)
    mma_gemm<<<g512, 256>>>(x, pwt + WT_Q,  tq_b,   pq,    N, HD_, D_);
    mma_gemm<<<g512, 256>>>(x, pwt + WT_K,  tk_b,   pk,    N, HD_, D_);
    mma_gemm<<<g512, 256>>>(x, pwt + WT_V,  tv_b,   pv,    N, HD_, D_);
    mma_gemm<<<g512, 256>>>(x, pwt + WT_G,  nullptr, pg,   N, HD_, D_);
    mma_gemm<<<g128, 256>>>(x, pwt + WT_WR, nullptr, pxsr, N, D_, D_);
    mma_gemm<<<g128, 256>>>(x, pwt + WT_SKIP, tskip_b, pskip, N, D_, D_);

    // edge phases: warp per (node, head), 2 nodes per 256-thread block
    int nb2 = (N + 1) / 2;
    k_asad<<<(N + 7) / 8, 256>>>(att_src, att_dst, N);
    k_trans_sage<<<nb2, 256>>>(src, ea, te_W, x, gate_a, N);
    k_gat<<<nb2, 256>>>(src, gat_bias, gate_n, N);

    // SAGE linear on mean, then short branch write
    mma_gemm<<<g128, 256>>>(pmean, pwt + WT_WL, sage_b, psWl, N, D_, D_);
    k_short<<<(N * D_ + 255) / 256, 256>>>(gate_s, N);

    // fusion GEMM (K=384) + epilogue
    mma_gemm<<<g128, 256>>>(pxcat, pwt + WT_FUS, fus_b, pfpre, N, D_, 3 * D_);
    k_final<<<(N + 7) / 8, 256>>>(x, fus_g, fus_beta, norm_g, norm_b, (float*)d_out, N);
}

// round 13
// speedup vs baseline: 1.3732x; 1.0174x over previous
#include <cuda_runtime.h>
#include <math.h>
#include <stdint.h>

#define D_   128
#define H_   4
#define HD_  512
#define ED_  16
#define QKVG 2048
#define MAXN 50000
#define MAXE 150000

// ---------------- scratch (device globals; no allocations allowed) ----------------
__device__ float g_qkvg[(size_t)MAXN * QKVG];   // per node: [q(512) k(512) v(512) g(512)]
__device__ float g_bias4[QKVG];
__device__ float g_xsr[(size_t)MAXN * D_];
__device__ float g_skip[(size_t)MAXN * D_];
__device__ float g_mean[(size_t)MAXN * D_];
__device__ float g_sWl[(size_t)MAXN * D_];
__device__ float g_fpre[(size_t)MAXN * D_];
__device__ float g_xcat[(size_t)MAXN * 3 * D_];
__device__ float g_as[MAXN * H_];
__device__ float g_ad[MAXN * H_];
__device__ int   g_deg[MAXN];
__device__ int   g_cur[MAXN];
__device__ int   g_rowptr[MAXN + 1];
__device__ int   g_eidx[MAXE];
// transposed tf32-rounded weights
__device__ float g_wt[4 * HD_ * D_ + 3 * D_ * D_ + D_ * 3 * D_];

#define WT_Q    0
#define WT_K    (HD_ * D_)
#define WT_V    (2 * HD_ * D_)
#define WT_G    (3 * HD_ * D_)
#define WT_WR   (4 * HD_ * D_)
#define WT_SKIP (4 * HD_ * D_ + D_ * D_)
#define WT_WL   (4 * HD_ * D_ + 2 * D_ * D_)
#define WT_FUS  (4 * HD_ * D_ + 3 * D_ * D_)

__device__ __forceinline__ uint32_t f2tf32(float v) {
    uint32_t r;
    asm("cvt.rna.tf32.f32 %0, %1;" : "=r"(r) : "f"(v));
    return r;
}

__device__ __forceinline__ float wredsum(float v) {
    v += __shfl_xor_sync(0xffffffffu, v, 16);
    v += __shfl_xor_sync(0xffffffffu, v, 8);
    v += __shfl_xor_sync(0xffffffffu, v, 4);
    v += __shfl_xor_sync(0xffffffffu, v, 2);
    v += __shfl_xor_sync(0xffffffffu, v, 1);
    return v;
}
__device__ __forceinline__ float lrelu02(float x) { return x > 0.f ? x : 0.2f * x; }
__device__ __forceinline__ float sigm(float x) { return 1.f / (1.f + __expf(-x)); }

// ---------------- weight transpose + tf32 round: W[K][Nc] -> Wt[Nc][K] ----------------
__global__ void k_transpose(const float* __restrict__ W, float* __restrict__ Wt, int K, int Nc) {
    int i = blockIdx.x * blockDim.x + threadIdx.x;
    if (i < K * Nc) {
        int k = i / Nc, n = i % Nc;
        ((uint32_t*)Wt)[(size_t)n * K + k] = f2tf32(W[i]);
    }
}

// concat bias for fused qkvg GEMM
__global__ void k_catbias(const float* __restrict__ qb, const float* __restrict__ kb,
                          const float* __restrict__ vb) {
    int i = blockIdx.x * blockDim.x + threadIdx.x;
    if (i < HD_) {
        g_bias4[i] = qb[i];
        g_bias4[HD_ + i] = kb[i];
        g_bias4[2 * HD_ + i] = vb[i];
        g_bias4[3 * HD_ + i] = 0.f;
    }
}

// ---------------- mma.sync tf32 GEMM: C[M,Nc] = A[M,K] @ Bt^T (+bias) ----------------
#define PITCH 136

__global__ void __launch_bounds__(256)
mma_gemm(const float* __restrict__ A, const float* __restrict__ Bt,
         const float* __restrict__ bias, float* __restrict__ C,
         int M, int Nc, int K) {
    __shared__ float As[32][PITCH];
    __shared__ float Bs[32][PITCH];
    int tid = threadIdx.x, wid = tid >> 5, lane = tid & 31;
    int rowStart = blockIdx.y * 128, colStart = blockIdx.x * 128;
    int warp_m = (wid >> 2) * 64;
    int warp_n = (wid & 3) * 32;
    int gq = lane >> 2;
    int tg = lane & 3;

    float acc[4][4][4];
    #pragma unroll
    for (int mt = 0; mt < 4; mt++)
        #pragma unroll
        for (int nt = 0; nt < 4; nt++)
            #pragma unroll
            for (int c = 0; c < 4; c++) acc[mt][nt][c] = 0.f;

    int lrow = tid & 127;
    int kqBase = (tid >> 7) * 4;
    int gr = rowStart + lrow;

    for (int k0 = 0; k0 < K; k0 += 32) {
        #pragma unroll
        for (int i = 0; i < 4; i++) {
            int kq = kqBase + i;
            float4 av = make_float4(0.f, 0.f, 0.f, 0.f);
            if (gr < M) av = *(const float4*)(A + (size_t)gr * K + k0 + (kq << 2));
            As[(kq << 2) + 0][lrow] = __uint_as_float(f2tf32(av.x));
            As[(kq << 2) + 1][lrow] = __uint_as_float(f2tf32(av.y));
            As[(kq << 2) + 2][lrow] = __uint_as_float(f2tf32(av.z));
            As[(kq << 2) + 3][lrow] = __uint_as_float(f2tf32(av.w));
        }
        #pragma unroll
        for (int i = 0; i < 4; i++) {
            int kq = kqBase + i;
            float4 bv = *(const float4*)(Bt + (size_t)(colStart + lrow) * K + k0 + (kq << 2));
            Bs[(kq << 2) + 0][lrow] = bv.x;
            Bs[(kq << 2) + 1][lrow] = bv.y;
            Bs[(kq << 2) + 2][lrow] = bv.z;
            Bs[(kq << 2) + 3][lrow] = bv.w;
        }
        __syncthreads();

        #pragma unroll
        for (int kk = 0; kk < 4; kk++) {
            int kb = kk << 3;
            uint32_t a[4][4], b[4][2];
            #pragma unroll
            for (int mt = 0; mt < 4; mt++) {
                int m0 = warp_m + mt * 16 + gq;
                a[mt][0] = __float_as_uint(As[kb + tg][m0]);
                a[mt][1] = __float_as_uint(As[kb + tg][m0 + 8]);
                a[mt][2] = __float_as_uint(As[kb + tg + 4][m0]);
                a[mt][3] = __float_as_uint(As[kb + tg + 4][m0 + 8]);
            }
            #pragma unroll
            for (int nt = 0; nt < 4; nt++) {
                int n0 = warp_n + nt * 8 + gq;
                b[nt][0] = __float_as_uint(Bs[kb + tg][n0]);
                b[nt][1] = __float_as_uint(Bs[kb + tg + 4][n0]);
            }
            #pragma unroll
            for (int mt = 0; mt < 4; mt++)
                #pragma unroll
                for (int nt = 0; nt < 4; nt++) {
                    asm volatile(
                        "mma.sync.aligned.m16n8k8.row.col.f32.tf32.tf32.f32 "
                        "{%0,%1,%2,%3}, {%4,%5,%6,%7}, {%8,%9}, {%0,%1,%2,%3};"
                        : "+f"(acc[mt][nt][0]), "+f"(acc[mt][nt][1]),
                          "+f"(acc[mt][nt][2]), "+f"(acc[mt][nt][3])
                        : "r"(a[mt][0]), "r"(a[mt][1]), "r"(a[mt][2]), "r"(a[mt][3]),
                          "r"(b[nt][0]), "r"(b[nt][1]));
                }
        }
        __syncthreads();
    }

    #pragma unroll
    for (int mt = 0; mt < 4; mt++) {
        int r0 = rowStart + warp_m + mt * 16 + gq;
        #pragma unroll
        for (int nt = 0; nt < 4; nt++) {
            int cb = colStart + warp_n + nt * 8 + tg * 2;
            float b0 = bias ? bias[cb] : 0.f;
            float b1 = bias ? bias[cb + 1] : 0.f;
            if (r0 < M) {
                C[(size_t)r0 * Nc + cb]     = acc[mt][nt][0] + b0;
                C[(size_t)r0 * Nc + cb + 1] = acc[mt][nt][1] + b1;
            }
            if (r0 + 8 < M) {
                C[(size_t)(r0 + 8) * Nc + cb]     = acc[mt][nt][2] + b0;
                C[(size_t)(r0 + 8) * Nc + cb + 1] = acc[mt][nt][3] + b1;
            }
        }
    }
}

// ---------------- CSR build ----------------
__global__ void k_zero(int N) {
    int i = blockIdx.x * blockDim.x + threadIdx.x;
    if (i < N) { g_deg[i] = 0; g_cur[i] = 0; }
}
__global__ void k_count(const int* __restrict__ dst, int E) {
    int e = blockIdx.x * blockDim.x + threadIdx.x;
    if (e < E) atomicAdd(&g_deg[dst[e]], 1);
}
__global__ void k_scan(int N) {
    __shared__ int wsum[32];
    __shared__ int carry;
    int tid = threadIdx.x, lane = tid & 31, wid = tid >> 5;
    if (tid == 0) carry = 0;
    __syncthreads();
    for (int base = 0; base < N; base += 1024) {
        int i = base + tid;
        int v = (i < N) ? g_deg[i] : 0;
        int x = v;
        #pragma unroll
        for (int o = 1; o < 32; o <<= 1) {
            int y = __shfl_up_sync(0xffffffffu, x, o);
            if (lane >= o) x += y;
        }
        if (lane == 31) wsum[wid] = x;
        __syncthreads();
        if (wid == 0) {
            int wv = wsum[lane];
            #pragma unroll
            for (int o = 1; o < 32; o <<= 1) {
                int y = __shfl_up_sync(0xffffffffu, wv, o);
                if (lane >= o) wv += y;
            }
            wsum[lane] = wv;
        }
        __syncthreads();
        int woff = (wid > 0) ? wsum[wid - 1] : 0;
        int excl = x - v + woff;
        int c = carry;
        if (i < N) g_rowptr[i] = c + excl;
        int total = wsum[31];
        __syncthreads();
        if (tid == 0) carry = c + total;
        __syncthreads();
    }
    if (threadIdx.x == 0) g_rowptr[N] = carry;
}
__global__ void k_fill(const int* __restrict__ dst, int E) {
    int e = blockIdx.x * blockDim.x + threadIdx.x;
    if (e < E) {
        int d = dst[e];
        int p = atomicAdd(&g_cur[d], 1);
        g_eidx[g_rowptr[d] + p] = e;
    }
}

// ---------------- GAT attention coefficients (g slice at offset 1536) ----------------
__global__ void k_asad(const float* __restrict__ att_src, const float* __restrict__ att_dst, int N) {
    __shared__ float aS[HD_], aD[HD_];
    for (int i = threadIdx.x; i < HD_; i += blockDim.x) { aS[i] = att_src[i]; aD[i] = att_dst[i]; }
    __syncthreads();
    int warp = (blockIdx.x * blockDim.x + threadIdx.x) >> 5;
    int lane = threadIdx.x & 31;
    if (warp >= N) return;
    int n = warp;
    float ps[4] = {0, 0, 0, 0}, pd[4] = {0, 0, 0, 0};
    #pragma unroll
    for (int t = 0; t < 16; t++) {
        float gv = g_qkvg[(size_t)n * QKVG + 3 * HD_ + lane + 32 * t];
        ps[t >> 2] = fmaf(gv, aS[lane + 32 * t], ps[t >> 2]);
        pd[t >> 2] = fmaf(gv, aD[lane + 32 * t], pd[t >> 2]);
    }
    float s0 = wredsum(ps[0]), s1 = wredsum(ps[1]), s2 = wredsum(ps[2]), s3 = wredsum(ps[3]);
    float d0 = wredsum(pd[0]), d1 = wredsum(pd[1]), d2 = wredsum(pd[2]), d3 = wredsum(pd[3]);
    if (lane == 0) {
        g_as[n * 4 + 0] = s0; g_as[n * 4 + 1] = s1; g_as[n * 4 + 2] = s2; g_as[n * 4 + 3] = s3;
        g_ad[n * 4 + 0] = d0; g_ad[n * 4 + 1] = d1; g_ad[n * 4 + 2] = d2; g_ad[n * 4 + 3] = d3;
    }
}

// ---------------- TransformerConv + SAGE mean: warp per (node, head), 2-edge unroll ----------------
// qkvg row as float4[512]: q at c, k at 128+c, v at 256+c (c = head*32+lane)
__global__ void __launch_bounds__(256)
k_trans_sage(const int* __restrict__ src, const float* __restrict__ ea,
             const float* __restrict__ te_W, const float* __restrict__ x,
             const float* __restrict__ gate_attn, int N) {
    __shared__ float4 te_sm[ED_][D_];
    __shared__ float4 red[2][H_][32];
    for (int i = threadIdx.x; i < ED_ * D_; i += blockDim.x) {
        int j = i >> 7, c = i & 127;
        te_sm[j][c] = *(const float4*)(te_W + (size_t)j * HD_ + (c << 2));
    }
    __syncthreads();

    int w = threadIdx.x >> 5, lane = threadIdx.x & 31;
    int nl = w >> 2, head = w & 3;
    int n = blockIdx.x * 2 + nl;
    bool active = (n < N);
    const float scale = 0.08838834764831845f;

    float4 acc = make_float4(0.f, 0.f, 0.f, 0.f);
    float4 accx = make_float4(0.f, 0.f, 0.f, 0.f);
    float m = -INFINITY, ssum = 0.f;
    int deg = 0;

    if (active) {
        int c = head * 32 + lane;
        const float4* row_n = (const float4*)(g_qkvg + (size_t)n * QKVG);
        float4 q4 = row_n[c];
        int r0 = g_rowptr[n], r1 = g_rowptr[n + 1];
        deg = r1 - r0;
        int ei = r0;
        for (; ei + 1 < r1; ei += 2) {
            int eid0 = g_eidx[ei], eid1 = g_eidx[ei + 1];
            int s0 = src[eid0], s1 = src[eid1];
            const float4* row0 = (const float4*)(g_qkvg + (size_t)s0 * QKVG);
            const float4* row1 = (const float4*)(g_qkvg + (size_t)s1 * QKVG);
            if (head == 0) {
                float4 xv0 = ((const float4*)(x + (size_t)s0 * D_))[lane];
                float4 xv1 = ((const float4*)(x + (size_t)s1 * D_))[lane];
                accx.x += xv0.x + xv1.x; accx.y += xv0.y + xv1.y;
                accx.z += xv0.z + xv1.z; accx.w += xv0.w + xv1.w;
            }
            float eav0 = (lane < ED_) ? ea[(size_t)eid0 * ED_ + lane] : 0.f;
            float eav1 = (lane < ED_) ? ea[(size_t)eid1 * ED_ + lane] : 0.f;
            float4 k40 = row0[128 + c], k41 = row1[128 + c];
            float4 e0 = make_float4(0.f, 0.f, 0.f, 0.f);
            float4 e1 = make_float4(0.f, 0.f, 0.f, 0.f);
            #pragma unroll
            for (int j = 0; j < ED_; j++) {
                float a0 = __shfl_sync(0xffffffffu, eav0, j);
                float a1 = __shfl_sync(0xffffffffu, eav1, j);
                float4 t = te_sm[j][c];
                e0.x = fmaf(a0, t.x, e0.x); e0.y = fmaf(a0, t.y, e0.y);
                e0.z = fmaf(a0, t.z, e0.z); e0.w = fmaf(a0, t.w, e0.w);
                e1.x = fmaf(a1, t.x, e1.x); e1.y = fmaf(a1, t.y, e1.y);
                e1.z = fmaf(a1, t.z, e1.z); e1.w = fmaf(a1, t.w, e1.w);
            }
            float p0 = q4.x * (k40.x + e0.x) + q4.y * (k40.y + e0.y)
                     + q4.z * (k40.z + e0.z) + q4.w * (k40.w + e0.w);
            float p1 = q4.x * (k41.x + e1.x) + q4.y * (k41.y + e1.y)
                     + q4.z * (k41.z + e1.z) + q4.w * (k41.w + e1.w);
            float l0 = wredsum(p0) * scale;
            float l1 = wredsum(p1) * scale;
            float4 v40 = row0[256 + c], v41 = row1[256 + c];
            float nm = fmaxf(m, fmaxf(l0, l1));
            float sc = __expf(m - nm), w0 = __expf(l0 - nm), w1 = __expf(l1 - nm);
            ssum = ssum * sc + w0 + w1; m = nm;
            acc.x = fmaf(acc.x, sc, w0 * (v40.x + e0.x) + w1 * (v41.x + e1.x));
            acc.y = fmaf(acc.y, sc, w0 * (v40.y + e0.y) + w1 * (v41.y + e1.y));
            acc.z = fmaf(acc.z, sc, w0 * (v40.z + e0.z) + w1 * (v41.z + e1.z));
            acc.w = fmaf(acc.w, sc, w0 * (v40.w + e0.w) + w1 * (v41.w + e1.w));
        }
        if (ei < r1) {
            int eid = g_eidx[ei];
            int s = src[eid];
            const float4* row = (const float4*)(g_qkvg + (size_t)s * QKVG);
            if (head == 0) {
                float4 xv = ((const float4*)(x + (size_t)s * D_))[lane];
                accx.x += xv.x; accx.y += xv.y; accx.z += xv.z; accx.w += xv.w;
            }
            float eav = (lane < ED_) ? ea[(size_t)eid * ED_ + lane] : 0.f;
            float4 e = make_float4(0.f, 0.f, 0.f, 0.f);
            #pragma unroll
            for (int j = 0; j < ED_; j++) {
                float a = __shfl_sync(0xffffffffu, eav, j);
                float4 t = te_sm[j][c];
                e.x = fmaf(a, t.x, e.x); e.y = fmaf(a, t.y, e.y);
                e.z = fmaf(a, t.z, e.z); e.w = fmaf(a, t.w, e.w);
            }
            float4 k4 = row[128 + c];
            float p = q4.x * (k4.x + e.x) + q4.y * (k4.y + e.y)
                    + q4.z * (k4.z + e.z) + q4.w * (k4.w + e.w);
            float l = wredsum(p) * scale;
            float nm = fmaxf(m, l), sc = __expf(m - nm), wgt = __expf(l - nm);
            ssum = ssum * sc + wgt; m = nm;
            float4 v4 = row[256 + c];
            acc.x = fmaf(acc.x, sc, wgt * (v4.x + e.x));
            acc.y = fmaf(acc.y, sc, wgt * (v4.y + e.y));
            acc.z = fmaf(acc.z, sc, wgt * (v4.z + e.z));
            acc.w = fmaf(acc.w, sc, wgt * (v4.w + e.w));
        }
        float inv = 1.f / (ssum + 1e-16f);
        red[nl][head][lane] = make_float4(acc.x * inv, acc.y * inv, acc.z * inv, acc.w * inv);
        if (head == 0) {
            float invd = 1.f / fmaxf((float)deg, 1.f);
            ((float4*)(g_mean + (size_t)n * D_))[lane] =
                make_float4(accx.x * invd, accx.y * invd, accx.z * invd, accx.w * invd);
        }
    }
    __syncthreads();
    if (active && head == 0) {
        float ga = sigm(gate_attn[0]);
        float4 a0 = red[nl][0][lane], a1 = red[nl][1][lane];
        float4 a2 = red[nl][2][lane], a3 = red[nl][3][lane];
        float4 sk = ((const float4*)(g_skip + (size_t)n * D_))[lane];
        float4 o;
        o.x = fmaxf(0.25f * (a0.x + a1.x + a2.x + a3.x) + sk.x, 0.f) * ga;
        o.y = fmaxf(0.25f * (a0.y + a1.y + a2.y + a3.y) + sk.y, 0.f) * ga;
        o.z = fmaxf(0.25f * (a0.z + a1.z + a2.z + a3.z) + sk.z, 0.f) * ga;
        o.w = fmaxf(0.25f * (a0.w + a1.w + a2.w + a3.w) + sk.w, 0.f) * ga;
        *(float4*)(g_xcat + (size_t)n * 384 + 128 + (lane << 2)) = o;
    }
}

// ---------------- GAT: warp per (node, head), 2-edge unroll (g slice at 384+c) ----------------
__global__ void __launch_bounds__(256)
k_gat(const int* __restrict__ src, const float* __restrict__ gat_bias,
      const float* __restrict__ gate_nb, int N) {
    __shared__ float4 red[2][H_][32];
    int w = threadIdx.x >> 5, lane = threadIdx.x & 31;
    int nl = w >> 2, head = w & 3;
    int n = blockIdx.x * 2 + nl;
    bool active = (n < N);

    if (active) {
        int c = 384 + head * 32 + lane;
        float ad = g_ad[n * 4 + head];
        float m = lrelu02(g_as[n * 4 + head] + ad);
        float ssum = 1.f;
        float4 acc = ((const float4*)(g_qkvg + (size_t)n * QKVG))[c];  // self-loop
        int r0 = g_rowptr[n], r1 = g_rowptr[n + 1];
        int ei = r0;
        for (; ei + 1 < r1; ei += 2) {
            int s0 = src[g_eidx[ei]], s1 = src[g_eidx[ei + 1]];
            float l0 = lrelu02(g_as[s0 * 4 + head] + ad);
            float l1 = lrelu02(g_as[s1 * 4 + head] + ad);
            float4 g40 = ((const float4*)(g_qkvg + (size_t)s0 * QKVG))[c];
            float4 g41 = ((const float4*)(g_qkvg + (size_t)s1 * QKVG))[c];
            float nm = fmaxf(m, fmaxf(l0, l1));
            float sc = __expf(m - nm), w0 = __expf(l0 - nm), w1 = __expf(l1 - nm);
            ssum = ssum * sc + w0 + w1; m = nm;
            acc.x = fmaf(acc.x, sc, w0 * g40.x + w1 * g41.x);
            acc.y = fmaf(acc.y, sc, w0 * g40.y + w1 * g41.y);
            acc.z = fmaf(acc.z, sc, w0 * g40.z + w1 * g41.z);
            acc.w = fmaf(acc.w, sc, w0 * g40.w + w1 * g41.w);
        }
        if (ei < r1) {
            int s = src[g_eidx[ei]];
            float l = lrelu02(g_as[s * 4 + head] + ad);
            float4 g4 = ((const float4*)(g_qkvg + (size_t)s * QKVG))[c];
            float nm = fmaxf(m, l), sc = __expf(m - nm), wgt = __expf(l - nm);
            ssum = ssum * sc + wgt; m = nm;
            acc.x = fmaf(acc.x, sc, wgt * g4.x);
            acc.y = fmaf(acc.y, sc, wgt * g4.y);
            acc.z = fmaf(acc.z, sc, wgt * g4.z);
            acc.w = fmaf(acc.w, sc, wgt * g4.w);
        }
        float inv = 1.f / (ssum + 1e-16f);
        red[nl][head][lane] = make_float4(acc.x * inv, acc.y * inv, acc.z * inv, acc.w * inv);
    }
    __syncthreads();
    if (active && head == 0) {
        float gn = sigm(gate_nb[0]);
        float4 a0 = red[nl][0][lane], a1 = red[nl][1][lane];
        float4 a2 = red[nl][2][lane], a3 = red[nl][3][lane];
        int d = lane << 2;
        float4 o;
        o.x = fmaxf(0.25f * (a0.x + a1.x + a2.x + a3.x) + gat_bias[d + 0], 0.f) * gn;
        o.y = fmaxf(0.25f * (a0.y + a1.y + a2.y + a3.y) + gat_bias[d + 1], 0.f) * gn;
        o.z = fmaxf(0.25f * (a0.z + a1.z + a2.z + a3.z) + gat_bias[d + 2], 0.f) * gn;
        o.w = fmaxf(0.25f * (a0.w + a1.w + a2.w + a3.w) + gat_bias[d + 3], 0.f) * gn;
        *(float4*)(g_xcat + (size_t)n * 384 + 256 + d) = o;
    }
}

// ---------------- short branch ----------------
__global__ void k_short(const float* __restrict__ gate_short, int N) {
    int i = blockIdx.x * blockDim.x + threadIdx.x;
    if (i >= N * D_) return;
    float gs = sigm(gate_short[0]);
    int n = i >> 7, d = i & 127;
    g_xcat[(size_t)n * 384 + d] = fmaxf(g_sWl[i] + g_xsr[i], 0.f) * gs;
}

// ---------------- fused epilogue: LN -> relu -> +x -> LN ----------------
__global__ void k_final(const float* __restrict__ x,
                        const float* __restrict__ fus_g, const float* __restrict__ fus_beta,
                        const float* __restrict__ norm_g, const float* __restrict__ norm_b,
                        float* __restrict__ out, int N) {
    int warp = (blockIdx.x * blockDim.x + threadIdx.x) >> 5;
    int lane = threadIdx.x & 31;
    if (warp >= N) return;
    int n = warp;
    float4 z4 = *(const float4*)(g_fpre + (size_t)n * D_ + (lane << 2));
    float z[4] = {z4.x, z4.y, z4.z, z4.w};
    float s = z[0] + z[1] + z[2] + z[3];
    float q = z[0] * z[0] + z[1] * z[1] + z[2] * z[2] + z[3] * z[3];
    s = wredsum(s); q = wredsum(q);
    float mu = s * (1.f / 128.f);
    float var = q * (1.f / 128.f) - mu * mu;
    float inv = rsqrtf(var + 1e-5f);
    float4 x4 = *(const float4*)(x + (size_t)n * D_ + (lane << 2));
    float xa[4] = {x4.x, x4.y, x4.z, x4.w};
    float t[4];
    #pragma unroll
    for (int c = 0; c < 4; c++) {
        int d = (lane << 2) + c;
        float ln = (z[c] - mu) * inv * fus_g[d] + fus_beta[d];
        t[c] = xa[c] + fmaxf(ln, 0.f);
    }
    float s2 = t[0] + t[1] + t[2] + t[3];
    float q2 = t[0] * t[0] + t[1] * t[1] + t[2] * t[2] + t[3] * t[3];
    s2 = wredsum(s2); q2 = wredsum(q2);
    mu = s2 * (1.f / 128.f);
    var = q2 * (1.f / 128.f) - mu * mu;
    inv = rsqrtf(var + 1e-5f);
    float o[4];
    #pragma unroll
    for (int c = 0; c < 4; c++) {
        int d = (lane << 2) + c;
        o[c] = (t[c] - mu) * inv * norm_g[d] + norm_b[d];
    }
    *(float4*)(out + (size_t)n * D_ + (lane << 2)) = make_float4(o[0], o[1], o[2], o[3]);
}

// ---------------- host ----------------
extern "C" void kernel_launch(void* const* d_in, const int* in_sizes, int n_in,
                              void* d_out, int out_size) {
    const float* x        = (const float*)d_in[0];
    const int*   ei       = (const int*)d_in[1];
    const float* ea       = (const float*)d_in[2];
    const float* sage_Wl  = (const float*)d_in[3];
    const float* sage_Wr  = (const float*)d_in[4];
    const float* sage_b   = (const float*)d_in[5];
    const float* tq_W     = (const float*)d_in[6];
    const float* tq_b     = (const float*)d_in[7];
    const float* tk_W     = (const float*)d_in[8];
    const float* tk_b     = (const float*)d_in[9];
    const float* tv_W     = (const float*)d_in[10];
    const float* tv_b     = (const float*)d_in[11];
    const float* te_W     = (const float*)d_in[12];
    const float* tskip_W  = (const float*)d_in[13];
    const float* tskip_b  = (const float*)d_in[14];
    const float* gat_W    = (const float*)d_in[15];
    const float* att_src  = (const float*)d_in[16];
    const float* att_dst  = (const float*)d_in[17];
    const float* gat_bias = (const float*)d_in[18];
    const float* gate_s   = (const float*)d_in[19];
    const float* gate_a   = (const float*)d_in[20];
    const float* gate_n   = (const float*)d_in[21];
    const float* fus_W    = (const float*)d_in[22];
    const float* fus_b    = (const float*)d_in[23];
    const float* fus_g    = (const float*)d_in[24];
    const float* fus_beta = (const float*)d_in[25];
    const float* norm_g   = (const float*)d_in[26];
    const float* norm_b   = (const float*)d_in[27];

    int N = in_sizes[0] / D_;
    int E = in_sizes[1] / 2;
    const int* src = ei;
    const int* dst = ei + E;

    static float *pqkvg = nullptr, *pbias4, *pxsr, *pskip, *pmean, *psWl, *pfpre, *pxcat, *pwt;
    if (!pqkvg) {
        cudaGetSymbolAddress((void**)&pqkvg, g_qkvg);
        cudaGetSymbolAddress((void**)&pbias4, g_bias4);
        cudaGetSymbolAddress((void**)&pxsr,  g_xsr);
        cudaGetSymbolAddress((void**)&pskip, g_skip);
        cudaGetSymbolAddress((void**)&pmean, g_mean);
        cudaGetSymbolAddress((void**)&psWl,  g_sWl);
        cudaGetSymbolAddress((void**)&pfpre, g_fpre);
        cudaGetSymbolAddress((void**)&pxcat, g_xcat);
        cudaGetSymbolAddress((void**)&pwt,   g_wt);
    }

    // CSR by destination
    k_zero<<<(N + 255) / 256, 256>>>(N);
    k_count<<<(E + 255) / 256, 256>>>(dst, E);
    k_scan<<<1, 1024>>>(N);
    k_fill<<<(E + 255) / 256, 256>>>(dst, E);

    // weight transposes + tf32 rounding (WT_Q..WT_G contiguous -> one [2048][128] B)
    int tb = 256;
    k_transpose<<<(D_ * HD_ + tb - 1) / tb, tb>>>(tq_W,    pwt + WT_Q,    D_, HD_);
    k_transpose<<<(D_ * HD_ + tb - 1) / tb, tb>>>(tk_W,    pwt + WT_K,    D_, HD_);
    k_transpose<<<(D_ * HD_ + tb - 1) / tb, tb>>>(tv_W,    pwt + WT_V,    D_, HD_);
    k_transpose<<<(D_ * HD_ + tb - 1) / tb, tb>>>(gat_W,   pwt + WT_G,    D_, HD_);
    k_transpose<<<(D_ * D_ + tb - 1) / tb, tb>>>(sage_Wr,  pwt + WT_WR,   D_, D_);
    k_transpose<<<(D_ * D_ + tb - 1) / tb, tb>>>(tskip_W,  pwt + WT_SKIP, D_, D_);
    k_transpose<<<(D_ * D_ + tb - 1) / tb, tb>>>(sage_Wl,  pwt + WT_WL,   D_, D_);
    k_transpose<<<(3 * D_ * D_ + tb - 1) / tb, tb>>>(fus_W, pwt + WT_FUS, 3 * D_, D_);
    k_catbias<<<(HD_ + tb - 1) / tb, tb>>>(tq_b, tk_b, tv_b);

    int mt = (N + 127) / 128;
    dim3 gqkvg(QKVG / 128, mt);
    dim3 g128(1, mt);

    // fused q/k/v/g projection (one GEMM, interleaved output) + the two D->D projections
    mma_gemm<<<gqkvg, 256>>>(x, pwt + WT_Q, pbias4, pqkvg, N, QKVG, D_);
    mma_gemm<<<g128, 256>>>(x, pwt + WT_WR, nullptr, pxsr, N, D_, D_);
    mma_gemm<<<g128, 256>>>(x, pwt + WT_SKIP, tskip_b, pskip, N, D_, D_);

    // edge phases: warp per (node, head), 2 nodes per 256-thread block
    int nb2 = (N + 1) / 2;
    k_asad<<<(N + 7) / 8, 256>>>(att_src, att_dst, N);
    k_trans_sage<<<nb2, 256>>>(src, ea, te_W, x, gate_a, N);
    k_gat<<<nb2, 256>>>(src, gat_bias, gate_n, N);

    // SAGE linear on mean, then short branch write
    mma_gemm<<<g128, 256>>>(pmean, pwt + WT_WL, sage_b, psWl, N, D_, D_);
    k_short<<<(N * D_ + 255) / 256, 256>>>(gate_s, N);

    // fusion GEMM (K=384) + epilogue
    mma_gemm<<<g128, 256>>>(pxcat, pwt + WT_FUS, fus_b, pfpre, N, D_, 3 * D_);
    k_final<<<(N + 7) / 8, 256>>>(x, fus_g, fus_beta, norm_g, norm_b, (float*)d_out, N);
}

// round 16
// speedup vs baseline: 1.4504x; 1.0563x over previous
#include <cuda_runtime.h>
#include <math.h>
#include <stdint.h>

#define D_   128
#define H_   4
#define HD_  512
#define ED_  16
#define QKVG 2048
#define MAXN 50000
#define MAXE 150000

// ---------------- scratch (device globals; no allocations allowed) ----------------
__device__ float g_qkvg[(size_t)MAXN * QKVG];   // per node: [q(512) k(512) v(512) g(512)]
__device__ float g_bias4[QKVG];
__device__ float g_xsr[(size_t)MAXN * D_];
__device__ float g_skip[(size_t)MAXN * D_];
__device__ float g_mean[(size_t)MAXN * D_];
__device__ float g_sWl[(size_t)MAXN * D_];
__device__ float g_fpre[(size_t)MAXN * D_];
__device__ float g_xcat[(size_t)MAXN * 3 * D_];
__device__ float g_as[MAXN * H_];
__device__ float g_ad[MAXN * H_];
__device__ int   g_deg[MAXN];
__device__ int   g_cur[MAXN];
__device__ int   g_rowptr[MAXN + 1];
__device__ int   g_eidx[MAXE];
__device__ float g_wt[4 * HD_ * D_ + 3 * D_ * D_ + D_ * 3 * D_];

#define WT_Q    0
#define WT_K    (HD_ * D_)
#define WT_V    (2 * HD_ * D_)
#define WT_G    (3 * HD_ * D_)
#define WT_WR   (4 * HD_ * D_)
#define WT_SKIP (4 * HD_ * D_ + D_ * D_)
#define WT_WL   (4 * HD_ * D_ + 2 * D_ * D_)
#define WT_FUS  (4 * HD_ * D_ + 3 * D_ * D_)

__device__ __forceinline__ uint32_t f2tf32(float v) {
    uint32_t r;
    asm("cvt.rna.tf32.f32 %0, %1;" : "=r"(r) : "f"(v));
    return r;
}
__device__ __forceinline__ uint32_t smem_u32(const void* p) {
    return (uint32_t)__cvta_generic_to_shared(p);
}
__device__ __forceinline__ float wredsum(float v) {
    v += __shfl_xor_sync(0xffffffffu, v, 16);
    v += __shfl_xor_sync(0xffffffffu, v, 8);
    v += __shfl_xor_sync(0xffffffffu, v, 4);
    v += __shfl_xor_sync(0xffffffffu, v, 2);
    v += __shfl_xor_sync(0xffffffffu, v, 1);
    return v;
}
__device__ __forceinline__ float lrelu02(float x) { return x > 0.f ? x : 0.2f * x; }
__device__ __forceinline__ float sigm(float x) { return 1.f / (1.f + __expf(-x)); }

// ---------------- weight transpose + tf32 round: W[K][Nc] -> Wt[Nc][K] ----------------
__global__ void k_transpose(const float* __restrict__ W, float* __restrict__ Wt, int K, int Nc) {
    int i = blockIdx.x * blockDim.x + threadIdx.x;
    if (i < K * Nc) {
        int k = i / Nc, n = i % Nc;
        ((uint32_t*)Wt)[(size_t)n * K + k] = f2tf32(W[i]);
    }
}

__global__ void k_catbias(const float* __restrict__ qb, const float* __restrict__ kb,
                          const float* __restrict__ vb) {
    int i = blockIdx.x * blockDim.x + threadIdx.x;
    if (i < HD_) {
        g_bias4[i] = qb[i];
        g_bias4[HD_ + i] = kb[i];
        g_bias4[2 * HD_ + i] = vb[i];
        g_bias4[3 * HD_ + i] = 0.f;
    }
}

// ---------------- cp.async double-buffered mma.sync tf32 GEMM ----------------
// tiles m-major [128][36] (pitch 36 -> conflict-free frag LDS), 2 stages, dyn smem.
#define TPITCH 36
#define STAGE_F (128 * TPITCH)              // floats per tile per stage
#define TC_SMEM (4 * STAGE_F * 4)           // 2 arrays x 2 stages, bytes = 73728

__global__ void __launch_bounds__(256)
mma_gemm(const float* __restrict__ A, const float* __restrict__ Bt,
         const float* __restrict__ bias, float* __restrict__ C,
         int M, int Nc, int K) {
    extern __shared__ float sm[];
    float* Asm = sm;                        // [2][128][36]
    float* Bsm = sm + 2 * STAGE_F;          // [2][128][36]
    int tid = threadIdx.x, wid = tid >> 5, lane = tid & 31;
    int rowStart = blockIdx.y * 128, colStart = blockIdx.x * 128;
    int warp_m = (wid >> 2) * 64;
    int warp_n = (wid & 3) * 32;
    int gq = lane >> 2;
    int tg = lane & 3;

    float acc[4][4][4];
    #pragma unroll
    for (int mt = 0; mt < 4; mt++)
        #pragma unroll
        for (int nt = 0; nt < 4; nt++)
            #pragma unroll
            for (int c = 0; c < 4; c++) acc[mt][nt][c] = 0.f;

    int lrow = tid & 127;
    int kqBase = (tid >> 7) * 4;
    int gr = rowStart + lrow;
    int abytes = (gr < M) ? 16 : 0;         // zero-fill OOB A rows
    int chunks = K >> 5;

    // prologue: chunk 0 -> stage 0
    {
        int k0 = 0;
        #pragma unroll
        for (int i = 0; i < 4; i++) {
            int kq = kqBase + i;
            uint32_t dA = smem_u32(&Asm[lrow * TPITCH + (kq << 2)]);
            const float* gA = A + (size_t)gr * K + k0 + (kq << 2);
            asm volatile("cp.async.cg.shared.global [%0], [%1], 16, %2;" :: "r"(dA), "l"(gA), "r"(abytes));
            uint32_t dB = smem_u32(&Bsm[lrow * TPITCH + (kq << 2)]);
            const float* gB = Bt + (size_t)(colStart + lrow) * K + k0 + (kq << 2);
            asm volatile("cp.async.cg.shared.global [%0], [%1], 16;" :: "r"(dB), "l"(gB));
        }
        asm volatile("cp.async.commit_group;");
    }

    for (int ch = 0; ch < chunks; ch++) {
        int cur = ch & 1;
        if (ch + 1 < chunks) {
            int nxt = cur ^ 1;
            int k0 = (ch + 1) << 5;
            #pragma unroll
            for (int i = 0; i < 4; i++) {
                int kq = kqBase + i;
                uint32_t dA = smem_u32(&Asm[nxt * STAGE_F + lrow * TPITCH + (kq << 2)]);
                const float* gA = A + (size_t)gr * K + k0 + (kq << 2);
                asm volatile("cp.async.cg.shared.global [%0], [%1], 16, %2;" :: "r"(dA), "l"(gA), "r"(abytes));
                uint32_t dB = smem_u32(&Bsm[nxt * STAGE_F + lrow * TPITCH + (kq << 2)]);
                const float* gB = Bt + (size_t)(colStart + lrow) * K + k0 + (kq << 2);
                asm volatile("cp.async.cg.shared.global [%0], [%1], 16;" :: "r"(dB), "l"(gB));
            }
            asm volatile("cp.async.commit_group;");
            asm volatile("cp.async.wait_group 1;");
        } else {
            asm volatile("cp.async.wait_group 0;");
        }
        __syncthreads();

        const float* Ac = Asm + cur * STAGE_F;
        const float* Bc = Bsm + cur * STAGE_F;
        #pragma unroll
        for (int kk = 0; kk < 4; kk++) {
            int kb = kk << 3;
            uint32_t a[4][4], b[4][2];
            #pragma unroll
            for (int mt = 0; mt < 4; mt++) {
                int m0 = warp_m + mt * 16 + gq;
                a[mt][0] = __float_as_uint(Ac[m0 * TPITCH + kb + tg]);
                a[mt][1] = __float_as_uint(Ac[(m0 + 8) * TPITCH + kb + tg]);
                a[mt][2] = __float_as_uint(Ac[m0 * TPITCH + kb + tg + 4]);
                a[mt][3] = __float_as_uint(Ac[(m0 + 8) * TPITCH + kb + tg + 4]);
            }
            #pragma unroll
            for (int nt = 0; nt < 4; nt++) {
                int n0 = warp_n + nt * 8 + gq;
                b[nt][0] = __float_as_uint(Bc[n0 * TPITCH + kb + tg]);
                b[nt][1] = __float_as_uint(Bc[n0 * TPITCH + kb + tg + 4]);
            }
            #pragma unroll
            for (int mt = 0; mt < 4; mt++)
                #pragma unroll
                for (int nt = 0; nt < 4; nt++) {
                    asm volatile(
                        "mma.sync.aligned.m16n8k8.row.col.f32.tf32.tf32.f32 "
                        "{%0,%1,%2,%3}, {%4,%5,%6,%7}, {%8,%9}, {%0,%1,%2,%3};"
                        : "+f"(acc[mt][nt][0]), "+f"(acc[mt][nt][1]),
                          "+f"(acc[mt][nt][2]), "+f"(acc[mt][nt][3])
                        : "r"(a[mt][0]), "r"(a[mt][1]), "r"(a[mt][2]), "r"(a[mt][3]),
                          "r"(b[nt][0]), "r"(b[nt][1]));
                }
        }
        __syncthreads();
    }

    #pragma unroll
    for (int mt = 0; mt < 4; mt++) {
        int r0 = rowStart + warp_m + mt * 16 + gq;
        #pragma unroll
        for (int nt = 0; nt < 4; nt++) {
            int cb = colStart + warp_n + nt * 8 + tg * 2;
            float b0 = bias ? bias[cb] : 0.f;
            float b1 = bias ? bias[cb + 1] : 0.f;
            if (r0 < M) {
                C[(size_t)r0 * Nc + cb]     = acc[mt][nt][0] + b0;
                C[(size_t)r0 * Nc + cb + 1] = acc[mt][nt][1] + b1;
            }
            if (r0 + 8 < M) {
                C[(size_t)(r0 + 8) * Nc + cb]     = acc[mt][nt][2] + b0;
                C[(size_t)(r0 + 8) * Nc + cb + 1] = acc[mt][nt][3] + b1;
            }
        }
    }
}

// ---------------- CSR build ----------------
__global__ void k_zero(int N) {
    int i = blockIdx.x * blockDim.x + threadIdx.x;
    if (i < N) { g_deg[i] = 0; g_cur[i] = 0; }
}
__global__ void k_count(const int* __restrict__ dst, int E) {
    int e = blockIdx.x * blockDim.x + threadIdx.x;
    if (e < E) atomicAdd(&g_deg[dst[e]], 1);
}
__global__ void k_scan(int N) {
    __shared__ int wsum[32];
    __shared__ int carry;
    int tid = threadIdx.x, lane = tid & 31, wid = tid >> 5;
    if (tid == 0) carry = 0;
    __syncthreads();
    for (int base = 0; base < N; base += 1024) {
        int i = base + tid;
        int v = (i < N) ? g_deg[i] : 0;
        int x = v;
        #pragma unroll
        for (int o = 1; o < 32; o <<= 1) {
            int y = __shfl_up_sync(0xffffffffu, x, o);
            if (lane >= o) x += y;
        }
        if (lane == 31) wsum[wid] = x;
        __syncthreads();
        if (wid == 0) {
            int wv = wsum[lane];
            #pragma unroll
            for (int o = 1; o < 32; o <<= 1) {
                int y = __shfl_up_sync(0xffffffffu, wv, o);
                if (lane >= o) wv += y;
            }
            wsum[lane] = wv;
        }
        __syncthreads();
        int woff = (wid > 0) ? wsum[wid - 1] : 0;
        int excl = x - v + woff;
        int c = carry;
        if (i < N) g_rowptr[i] = c + excl;
        int total = wsum[31];
        __syncthreads();
        if (tid == 0) carry = c + total;
        __syncthreads();
    }
    if (threadIdx.x == 0) g_rowptr[N] = carry;
}
__global__ void k_fill(const int* __restrict__ dst, int E) {
    int e = blockIdx.x * blockDim.x + threadIdx.x;
    if (e < E) {
        int d = dst[e];
        int p = atomicAdd(&g_cur[d], 1);
        g_eidx[g_rowptr[d] + p] = e;
    }
}

// ---------------- GAT attention coefficients (g slice at offset 1536) ----------------
__global__ void k_asad(const float* __restrict__ att_src, const float* __restrict__ att_dst, int N) {
    __shared__ float aS[HD_], aD[HD_];
    for (int i = threadIdx.x; i < HD_; i += blockDim.x) { aS[i] = att_src[i]; aD[i] = att_dst[i]; }
    __syncthreads();
    int warp = (blockIdx.x * blockDim.x + threadIdx.x) >> 5;
    int lane = threadIdx.x & 31;
    if (warp >= N) return;
    int n = warp;
    float ps[4] = {0, 0, 0, 0}, pd[4] = {0, 0, 0, 0};
    #pragma unroll
    for (int t = 0; t < 16; t++) {
        float gv = g_qkvg[(size_t)n * QKVG + 3 * HD_ + lane + 32 * t];
        ps[t >> 2] = fmaf(gv, aS[lane + 32 * t], ps[t >> 2]);
        pd[t >> 2] = fmaf(gv, aD[lane + 32 * t], pd[t >> 2]);
    }
    float s0 = wredsum(ps[0]), s1 = wredsum(ps[1]), s2 = wredsum(ps[2]), s3 = wredsum(ps[3]);
    float d0 = wredsum(pd[0]), d1 = wredsum(pd[1]), d2 = wredsum(pd[2]), d3 = wredsum(pd[3]);
    if (lane == 0) {
        g_as[n * 4 + 0] = s0; g_as[n * 4 + 1] = s1; g_as[n * 4 + 2] = s2; g_as[n * 4 + 3] = s3;
        g_ad[n * 4 + 0] = d0; g_ad[n * 4 + 1] = d1; g_ad[n * 4 + 2] = d2; g_ad[n * 4 + 3] = d3;
    }
}

// ---------------- merged TransformerConv + GAT + SAGE mean: warp per (node, head) ----------------
// qkvg row as float4[512]: q at c, k at 128+c, v at 256+c, g at 384+c (c = head*32+lane)
__global__ void __launch_bounds__(256)
k_edge(const int* __restrict__ src, const float* __restrict__ ea,
       const float* __restrict__ te_W, const float* __restrict__ x,
       const float* __restrict__ gate_attn,
       const float* __restrict__ gat_bias, const float* __restrict__ gate_nb, int N) {
    __shared__ float4 te_sm[ED_][D_];         // 32 KB
    __shared__ float4 red_t[2][H_][32];       // 4 KB
    __shared__ float4 red_g[2][H_][32];       // 4 KB
    for (int i = threadIdx.x; i < ED_ * D_; i += blockDim.x) {
        int j = i >> 7, c = i & 127;
        te_sm[j][c] = *(const float4*)(te_W + (size_t)j * HD_ + (c << 2));
    }
    __syncthreads();

    int w = threadIdx.x >> 5, lane = threadIdx.x & 31;
    int nl = w >> 2, head = w & 3;
    int n = blockIdx.x * 2 + nl;
    bool active = (n < N);
    const float scale = 0.08838834764831845f;

    if (active) {
        int c = head * 32 + lane;
        const float4* row_n = (const float4*)(g_qkvg + (size_t)n * QKVG);
        float4 q4 = row_n[c];
        // transformer state
        float4 acc = make_float4(0.f, 0.f, 0.f, 0.f);
        float m = -INFINITY, ssum = 0.f;
        // gat state (self-loop init)
        float ad = g_ad[n * 4 + head];
        float mg = lrelu02(g_as[n * 4 + head] + ad);
        float sg = 1.f;
        float4 accg = row_n[384 + c];
        // sage
        float4 accx = make_float4(0.f, 0.f, 0.f, 0.f);

        int r0 = g_rowptr[n], r1 = g_rowptr[n + 1];
        int deg = r1 - r0;
        for (int ei = r0; ei < r1; ei++) {
            int eid = g_eidx[ei];
            int s = src[eid];
            const float4* row = (const float4*)(g_qkvg + (size_t)s * QKVG);
            if (head == 0) {
                float4 xv = ((const float4*)(x + (size_t)s * D_))[lane];
                accx.x += xv.x; accx.y += xv.y; accx.z += xv.z; accx.w += xv.w;
            }
            // prefetch all three row slices up-front (independent loads -> MLP 3)
            float4 k4 = row[128 + c];
            float4 v4 = row[256 + c];
            float4 g4 = row[384 + c];
            // edge embedding
            float eav = (lane < ED_) ? ea[(size_t)eid * ED_ + lane] : 0.f;
            float4 e = make_float4(0.f, 0.f, 0.f, 0.f);
            #pragma unroll
            for (int j = 0; j < ED_; j++) {
                float a = __shfl_sync(0xffffffffu, eav, j);
                float4 t = te_sm[j][c];
                e.x = fmaf(a, t.x, e.x); e.y = fmaf(a, t.y, e.y);
                e.z = fmaf(a, t.z, e.z); e.w = fmaf(a, t.w, e.w);
            }
            // transformer logit + online softmax
            float p = q4.x * (k4.x + e.x) + q4.y * (k4.y + e.y)
                    + q4.z * (k4.z + e.z) + q4.w * (k4.w + e.w);
            float l = wredsum(p) * scale;
            float nm = fmaxf(m, l), sc = __expf(m - nm), wgt = __expf(l - nm);
            ssum = ssum * sc + wgt; m = nm;
            acc.x = fmaf(acc.x, sc, wgt * (v4.x + e.x));
            acc.y = fmaf(acc.y, sc, wgt * (v4.y + e.y));
            acc.z = fmaf(acc.z, sc, wgt * (v4.z + e.z));
            acc.w = fmaf(acc.w, sc, wgt * (v4.w + e.w));
            // gat online softmax
            float lg = lrelu02(g_as[s * 4 + head] + ad);
            float nmg = fmaxf(mg, lg), scg = __expf(mg - nmg), wg = __expf(lg - nmg);
            sg = sg * scg + wg; mg = nmg;
            accg.x = fmaf(accg.x, scg, wg * g4.x);
            accg.y = fmaf(accg.y, scg, wg * g4.y);
            accg.z = fmaf(accg.z, scg, wg * g4.z);
            accg.w = fmaf(accg.w, scg, wg * g4.w);
        }
        float inv = 1.f / (ssum + 1e-16f);
        red_t[nl][head][lane] = make_float4(acc.x * inv, acc.y * inv, acc.z * inv, acc.w * inv);
        float invg = 1.f / (sg + 1e-16f);
        red_g[nl][head][lane] = make_float4(accg.x * invg, accg.y * invg, accg.z * invg, accg.w * invg);
        if (head == 0) {
            float invd = 1.f / fmaxf((float)deg, 1.f);
            ((float4*)(g_mean + (size_t)n * D_))[lane] =
                make_float4(accx.x * invd, accx.y * invd, accx.z * invd, accx.w * invd);
        }
    }
    __syncthreads();
    if (active && head == 0) {
        float ga = sigm(gate_attn[0]);
        float gn = sigm(gate_nb[0]);
        int d = lane << 2;
        {
            float4 a0 = red_t[nl][0][lane], a1 = red_t[nl][1][lane];
            float4 a2 = red_t[nl][2][lane], a3 = red_t[nl][3][lane];
            float4 sk = ((const float4*)(g_skip + (size_t)n * D_))[lane];
            float4 o;
            o.x = fmaxf(0.25f * (a0.x + a1.x + a2.x + a3.x) + sk.x, 0.f) * ga;
            o.y = fmaxf(0.25f * (a0.y + a1.y + a2.y + a3.y) + sk.y, 0.f) * ga;
            o.z = fmaxf(0.25f * (a0.z + a1.z + a2.z + a3.z) + sk.z, 0.f) * ga;
            o.w = fmaxf(0.25f * (a0.w + a1.w + a2.w + a3.w) + sk.w, 0.f) * ga;
            *(float4*)(g_xcat + (size_t)n * 384 + 128 + d) = o;
        }
        {
            float4 a0 = red_g[nl][0][lane], a1 = red_g[nl][1][lane];
            float4 a2 = red_g[nl][2][lane], a3 = red_g[nl][3][lane];
            float4 o;
            o.x = fmaxf(0.25f * (a0.x + a1.x + a2.x + a3.x) + gat_bias[d + 0], 0.f) * gn;
            o.y = fmaxf(0.25f * (a0.y + a1.y + a2.y + a3.y) + gat_bias[d + 1], 0.f) * gn;
            o.z = fmaxf(0.25f * (a0.z + a1.z + a2.z + a3.z) + gat_bias[d + 2], 0.f) * gn;
            o.w = fmaxf(0.25f * (a0.w + a1.w + a2.w + a3.w) + gat_bias[d + 3], 0.f) * gn;
            *(float4*)(g_xcat + (size_t)n * 384 + 256 + d) = o;
        }
    }
}

// ---------------- short branch ----------------
__global__ void k_short(const float* __restrict__ gate_short, int N) {
    int i = blockIdx.x * blockDim.x + threadIdx.x;
    if (i >= N * D_) return;
    float gs = sigm(gate_short[0]);
    int n = i >> 7, d = i & 127;
    g_xcat[(size_t)n * 384 + d] = fmaxf(g_sWl[i] + g_xsr[i], 0.f) * gs;
}

// ---------------- fused epilogue: LN -> relu -> +x -> LN ----------------
__global__ void k_final(const float* __restrict__ x,
                        const float* __restrict__ fus_g, const float* __restrict__ fus_beta,
                        const float* __restrict__ norm_g, const float* __restrict__ norm_b,
                        float* __restrict__ out, int N) {
    int warp = (blockIdx.x * blockDim.x + threadIdx.x) >> 5;
    int lane = threadIdx.x & 31;
    if (warp >= N) return;
    int n = warp;
    float4 z4 = *(const float4*)(g_fpre + (size_t)n * D_ + (lane << 2));
    float z[4] = {z4.x, z4.y, z4.z, z4.w};
    float s = z[0] + z[1] + z[2] + z[3];
    float q = z[0] * z[0] + z[1] * z[1] + z[2] * z[2] + z[3] * z[3];
    s = wredsum(s); q = wredsum(q);
    float mu = s * (1.f / 128.f);
    float var = q * (1.f / 128.f) - mu * mu;
    float inv = rsqrtf(var + 1e-5f);
    float4 x4 = *(const float4*)(x + (size_t)n * D_ + (lane << 2));
    float xa[4] = {x4.x, x4.y, x4.z, x4.w};
    float t[4];
    #pragma unroll
    for (int c = 0; c < 4; c++) {
        int d = (lane << 2) + c;
        float ln = (z[c] - mu) * inv * fus_g[d] + fus_beta[d];
        t[c] = xa[c] + fmaxf(ln, 0.f);
    }
    float s2 = t[0] + t[1] + t[2] + t[3];
    float q2 = t[0] * t[0] + t[1] * t[1] + t[2] * t[2] + t[3] * t[3];
    s2 = wredsum(s2); q2 = wredsum(q2);
    mu = s2 * (1.f / 128.f);
    var = q2 * (1.f / 128.f) - mu * mu;
    inv = rsqrtf(var + 1e-5f);
    float o[4];
    #pragma unroll
    for (int c = 0; c < 4; c++) {
        int d = (lane << 2) + c;
        o[c] = (t[c] - mu) * inv * norm_g[d] + norm_b[d];
    }
    *(float4*)(out + (size_t)n * D_ + (lane << 2)) = make_float4(o[0], o[1], o[2], o[3]);
}

// ---------------- host ----------------
extern "C" void kernel_launch(void* const* d_in, const int* in_sizes, int n_in,
                              void* d_out, int out_size) {
    const float* x        = (const float*)d_in[0];
    const int*   ei       = (const int*)d_in[1];
    const float* ea       = (const float*)d_in[2];
    const float* sage_Wl  = (const float*)d_in[3];
    const float* sage_Wr  = (const float*)d_in[4];
    const float* sage_b   = (const float*)d_in[5];
    const float* tq_W     = (const float*)d_in[6];
    const float* tq_b     = (const float*)d_in[7];
    const float* tk_W     = (const float*)d_in[8];
    const float* tk_b     = (const float*)d_in[9];
    const float* tv_W     = (const float*)d_in[10];
    const float* tv_b     = (const float*)d_in[11];
    const float* te_W     = (const float*)d_in[12];
    const float* tskip_W  = (const float*)d_in[13];
    const float* tskip_b  = (const float*)d_in[14];
    const float* gat_W    = (const float*)d_in[15];
    const float* att_src  = (const float*)d_in[16];
    const float* att_dst  = (const float*)d_in[17];
    const float* gat_bias = (const float*)d_in[18];
    const float* gate_s   = (const float*)d_in[19];
    const float* gate_a   = (const float*)d_in[20];
    const float* gate_n   = (const float*)d_in[21];
    const float* fus_W    = (const float*)d_in[22];
    const float* fus_b    = (const float*)d_in[23];
    const float* fus_g    = (const float*)d_in[24];
    const float* fus_beta = (const float*)d_in[25];
    const float* norm_g   = (const float*)d_in[26];
    const float* norm_b   = (const float*)d_in[27];

    int N = in_sizes[0] / D_;
    int E = in_sizes[1] / 2;
    const int* src = ei;
    const int* dst = ei + E;

    static float *pqkvg = nullptr, *pbias4, *pxsr, *pskip, *pmean, *psWl, *pfpre, *pxcat, *pwt;
    if (!pqkvg) {
        cudaGetSymbolAddress((void**)&pqkvg, g_qkvg);
        cudaGetSymbolAddress((void**)&pbias4, g_bias4);
        cudaGetSymbolAddress((void**)&pxsr,  g_xsr);
        cudaGetSymbolAddress((void**)&pskip, g_skip);
        cudaGetSymbolAddress((void**)&pmean, g_mean);
        cudaGetSymbolAddress((void**)&psWl,  g_sWl);
        cudaGetSymbolAddress((void**)&pfpre, g_fpre);
        cudaGetSymbolAddress((void**)&pxcat, g_xcat);
        cudaGetSymbolAddress((void**)&pwt,   g_wt);
        cudaFuncSetAttribute(mma_gemm, cudaFuncAttributeMaxDynamicSharedMemorySize, TC_SMEM);
    }

    // CSR by destination
    k_zero<<<(N + 255) / 256, 256>>>(N);
    k_count<<<(E + 255) / 256, 256>>>(dst, E);
    k_scan<<<1, 1024>>>(N);
    k_fill<<<(E + 255) / 256, 256>>>(dst, E);

    // weight transposes + tf32 rounding (WT_Q..WT_G contiguous -> one [2048][128] B)
    int tb = 256;
    k_transpose<<<(D_ * HD_ + tb - 1) / tb, tb>>>(tq_W,    pwt + WT_Q,    D_, HD_);
    k_transpose<<<(D_ * HD_ + tb - 1) / tb, tb>>>(tk_W,    pwt + WT_K,    D_, HD_);
    k_transpose<<<(D_ * HD_ + tb - 1) / tb, tb>>>(tv_W,    pwt + WT_V,    D_, HD_);
    k_transpose<<<(D_ * HD_ + tb - 1) / tb, tb>>>(gat_W,   pwt + WT_G,    D_, HD_);
    k_transpose<<<(D_ * D_ + tb - 1) / tb, tb>>>(sage_Wr,  pwt + WT_WR,   D_, D_);
    k_transpose<<<(D_ * D_ + tb - 1) / tb, tb>>>(tskip_W,  pwt + WT_SKIP, D_, D_);
    k_transpose<<<(D_ * D_ + tb - 1) / tb, tb>>>(sage_Wl,  pwt + WT_WL,   D_, D_);
    k_transpose<<<(3 * D_ * D_ + tb - 1) / tb, tb>>>(fus_W, pwt + WT_FUS, 3 * D_, D_);
    k_catbias<<<(HD_ + tb - 1) / tb, tb>>>(tq_b, tk_b, tv_b);

    int mt = (N + 127) / 128;
    dim3 gqkvg(QKVG / 128, mt);
    dim3 g128(1, mt);

    // fused q/k/v/g projection + the two D->D projections
    mma_gemm<<<gqkvg, 256, TC_SMEM>>>(x, pwt + WT_Q, pbias4, pqkvg, N, QKVG, D_);
    mma_gemm<<<g128, 256, TC_SMEM>>>(x, pwt + WT_WR, nullptr, pxsr, N, D_, D_);
    mma_gemm<<<g128, 256, TC_SMEM>>>(x, pwt + WT_SKIP, tskip_b, pskip, N, D_, D_);

    // edge phase: merged transformer+GAT+SAGE, warp per (node, head)
    int nb2 = (N + 1) / 2;
    k_asad<<<(N + 7) / 8, 256>>>(att_src, att_dst, N);
    k_edge<<<nb2, 256>>>(src, ea, te_W, x, gate_a, gat_bias, gate_n, N);

    // SAGE linear on mean, then short branch write
    mma_gemm<<<g128, 256, TC_SMEM>>>(pmean, pwt + WT_WL, sage_b, psWl, N, D_, D_);
    k_short<<<(N * D_ + 255) / 256, 256>>>(gate_s, N);

    // fusion GEMM (K=384) + epilogue
    mma_gemm<<<g128, 256, TC_SMEM>>>(pxcat, pwt + WT_FUS, fus_b, pfpre, N, D_, 3 * D_);
    k_final<<<(N + 7) / 8, 256>>>(x, fus_g, fus_beta, norm_g, norm_b, (float*)d_out, N);
}